// round 1
// baseline (speedup 1.0000x reference)
#include <cuda_runtime.h>
#include <math.h>

// Problem constants
static constexpr int B  = 2;
static constexpr int S  = 2048;
static constexpr int DM = 1024;
static constexpr int H  = 16;
static constexpr int D  = 64;        // DM / H
static constexpr int MTOK = B * S;   // 4096 tokens

// Scratch (device globals: allocation-free rule)
__device__ float g_q[B * H * S * D];     // (B,H,S,D)
__device__ float g_k[B * H * S * D];
__device__ float g_v[B * H * S * D];
__device__ float g_attn[B * S * DM];     // merged heads (B,S,DM)

// ---------------------------------------------------------------------------
// Projection GEMM: out = X[MTOK, DM] @ W[DM, DM] + bias
// SPLIT=true  -> write head-split layout (B,H,S,D)
// SPLIT=false -> write row-major (MTOK, DM)
// ---------------------------------------------------------------------------
template <bool SPLIT>
__global__ __launch_bounds__(256) void proj_kernel(
    const float* __restrict__ X, const float* __restrict__ W,
    const float* __restrict__ bias, float* __restrict__ out)
{
    constexpr int BM = 64, BN = 64, BK = 16;
    __shared__ float As[BK][BM + 1];   // As[k][m], padded (conflict-free stores)
    __shared__ float Bs[BK][BN];       // Bs[k][n]

    const int tid = threadIdx.x;
    const int m0 = blockIdx.y * BM;
    const int n0 = blockIdx.x * BN;
    const int ty = tid >> 4, tx = tid & 15;

    float acc[4][4] = {};

    for (int k0 = 0; k0 < DM; k0 += BK) {
        #pragma unroll
        for (int t = 0; t < 4; t++) {          // A tile: 64x16
            int e = tid + t * 256;
            int m = e >> 4, kk = e & 15;
            As[kk][m] = X[(size_t)(m0 + m) * DM + k0 + kk];
        }
        #pragma unroll
        for (int t = 0; t < 4; t++) {          // B tile: 16x64
            int e = tid + t * 256;
            int kk = e >> 6, n = e & 63;
            Bs[kk][n] = W[(size_t)(k0 + kk) * DM + n0 + n];
        }
        __syncthreads();
        #pragma unroll
        for (int kk = 0; kk < BK; kk++) {
            float a[4], bb[4];
            #pragma unroll
            for (int i = 0; i < 4; i++) a[i]  = As[kk][ty * 4 + i];
            #pragma unroll
            for (int j = 0; j < 4; j++) bb[j] = Bs[kk][tx * 4 + j];
            #pragma unroll
            for (int i = 0; i < 4; i++)
                #pragma unroll
                for (int j = 0; j < 4; j++)
                    acc[i][j] = fmaf(a[i], bb[j], acc[i][j]);
        }
        __syncthreads();
    }

    #pragma unroll
    for (int i = 0; i < 4; i++) {
        const int row = m0 + ty * 4 + i;
        #pragma unroll
        for (int j = 0; j < 4; j++) {
            const int col = n0 + tx * 4 + j;
            const float v = acc[i][j] + bias[col];
            if (SPLIT) {
                const int b = row / S, s = row % S;
                const int h = col / D, d = col % D;
                out[(((size_t)(b * H + h)) * S + s) * D + d] = v;
            } else {
                out[(size_t)row * DM + col] = v;
            }
        }
    }
}

// ---------------------------------------------------------------------------
// Logits: L[bh, i, j] = dot(q[bh,i,:], k[bh,j,:]) / sqrt(D)
// One block computes a 64x64 tile; K-dim (D=64) fully in smem.
// ---------------------------------------------------------------------------
__global__ __launch_bounds__(256) void logits_kernel(float* __restrict__ Wout)
{
    __shared__ float Qs[64][D + 1];   // Qs[row][d], padded
    __shared__ float Ks[64][D + 1];

    const int bh = blockIdx.z;
    const int i0 = blockIdx.y * 64;
    const int j0 = blockIdx.x * 64;
    const float* qb = g_q + (size_t)bh * S * D;
    const float* kb = g_k + (size_t)bh * S * D;
    const int tid = threadIdx.x;

    #pragma unroll
    for (int t = 0; t < 16; t++) {
        int e = tid + t * 256;
        int r = e >> 6, d = e & 63;
        Qs[r][d] = qb[(size_t)(i0 + r) * D + d];
        Ks[r][d] = kb[(size_t)(j0 + r) * D + d];
    }
    __syncthreads();

    const int ty = tid >> 4, tx = tid & 15;
    float acc[4][4] = {};
    #pragma unroll 16
    for (int d = 0; d < D; d++) {
        float a[4], bb[4];
        #pragma unroll
        for (int i = 0; i < 4; i++) a[i]  = Qs[ty * 4 + i][d];
        #pragma unroll
        for (int j = 0; j < 4; j++) bb[j] = Ks[tx * 4 + j][d];
        #pragma unroll
        for (int i = 0; i < 4; i++)
            #pragma unroll
            for (int j = 0; j < 4; j++)
                acc[i][j] = fmaf(a[i], bb[j], acc[i][j]);
    }

    float* outb = Wout + (size_t)bh * S * S;
    const float scale = 0.125f;  // 1/sqrt(64)
    #pragma unroll
    for (int i = 0; i < 4; i++)
        #pragma unroll
        for (int j = 0; j < 4; j++)
            outb[(size_t)(i0 + ty * 4 + i) * S + (j0 + tx * 4 + j)] =
                acc[i][j] * scale;
}

// ---------------------------------------------------------------------------
// Row softmax in place: one block per row of length S=2048.
// ---------------------------------------------------------------------------
__global__ __launch_bounds__(256) void softmax_kernel(float* __restrict__ Wt)
{
    __shared__ float red[256];
    float* p = Wt + (size_t)blockIdx.x * S;
    const int tid = threadIdx.x;

    float v[8];
    float m = -1e30f;
    #pragma unroll
    for (int t = 0; t < 8; t++) { v[t] = p[tid + t * 256]; m = fmaxf(m, v[t]); }

    red[tid] = m; __syncthreads();
    #pragma unroll
    for (int off = 128; off > 0; off >>= 1) {
        if (tid < off) red[tid] = fmaxf(red[tid], red[tid + off]);
        __syncthreads();
    }
    m = red[0];
    __syncthreads();

    float sum = 0.f;
    #pragma unroll
    for (int t = 0; t < 8; t++) { v[t] = __expf(v[t] - m); sum += v[t]; }

    red[tid] = sum; __syncthreads();
    #pragma unroll
    for (int off = 128; off > 0; off >>= 1) {
        if (tid < off) red[tid] += red[tid + off];
        __syncthreads();
    }
    const float inv = 1.0f / red[0];

    #pragma unroll
    for (int t = 0; t < 8; t++) p[tid + t * 256] = v[t] * inv;
}

// ---------------------------------------------------------------------------
// attn = weights[bh, S, S] @ v[bh, S, D], written merged (B,S,DM)
// ---------------------------------------------------------------------------
__global__ __launch_bounds__(256) void attnv_kernel(const float* __restrict__ Wt)
{
    constexpr int BK = 16;
    __shared__ float Ws[BK][64 + 1];   // Ws[kk][m], padded
    __shared__ float Vs[BK][64];       // Vs[kk][d]

    const int bh = blockIdx.y;
    const int m0 = blockIdx.x * 64;
    const float* wb = Wt  + (size_t)bh * S * S;
    const float* vb = g_v + (size_t)bh * S * D;
    const int b = bh / H, h = bh % H;
    const int tid = threadIdx.x;
    const int ty = tid >> 4, tx = tid & 15;

    float acc[4][4] = {};

    for (int k0 = 0; k0 < S; k0 += BK) {
        #pragma unroll
        for (int t = 0; t < 4; t++) {          // weights tile 64x16
            int e = tid + t * 256;
            int m = e >> 4, kk = e & 15;
            Ws[kk][m] = wb[(size_t)(m0 + m) * S + k0 + kk];
        }
        #pragma unroll
        for (int t = 0; t < 4; t++) {          // v tile 16x64
            int e = tid + t * 256;
            int kk = e >> 6, d = e & 63;
            Vs[kk][d] = vb[(size_t)(k0 + kk) * D + d];
        }
        __syncthreads();
        #pragma unroll
        for (int kk = 0; kk < BK; kk++) {
            float a[4], bb[4];
            #pragma unroll
            for (int i = 0; i < 4; i++) a[i]  = Ws[kk][ty * 4 + i];
            #pragma unroll
            for (int j = 0; j < 4; j++) bb[j] = Vs[kk][tx * 4 + j];
            #pragma unroll
            for (int i = 0; i < 4; i++)
                #pragma unroll
                for (int j = 0; j < 4; j++)
                    acc[i][j] = fmaf(a[i], bb[j], acc[i][j]);
        }
        __syncthreads();
    }

    #pragma unroll
    for (int i = 0; i < 4; i++) {
        const int s = m0 + ty * 4 + i;
        #pragma unroll
        for (int j = 0; j < 4; j++) {
            const int d = tx * 4 + j;
            g_attn[((size_t)(b * S + s)) * DM + h * D + d] = acc[i][j];
        }
    }
}

// ---------------------------------------------------------------------------
extern "C" void kernel_launch(void* const* d_in, const int* in_sizes, int n_in,
                              void* d_out, int out_size)
{
    const float* Q  = (const float*)d_in[0];
    const float* K  = (const float*)d_in[1];
    const float* V  = (const float*)d_in[2];
    const float* Wq = (const float*)d_in[3];
    const float* bq = (const float*)d_in[4];
    const float* Wk = (const float*)d_in[5];
    const float* bk = (const float*)d_in[6];
    const float* Wv = (const float*)d_in[7];
    const float* bv = (const float*)d_in[8];
    const float* Wo = (const float*)d_in[9];
    const float* bo = (const float*)d_in[10];

    float* out     = (float*)d_out;                    // (B,S,DM)
    float* weights = out + (size_t)B * S * DM;         // (B,H,S,S)

    float *q_ptr, *k_ptr, *v_ptr, *attn_ptr;
    cudaGetSymbolAddress((void**)&q_ptr, g_q);
    cudaGetSymbolAddress((void**)&k_ptr, g_k);
    cudaGetSymbolAddress((void**)&v_ptr, g_v);
    cudaGetSymbolAddress((void**)&attn_ptr, g_attn);

    dim3 pgrid(DM / 64, MTOK / 64);   // (16, 64)

    proj_kernel<true><<<pgrid, 256>>>(Q, Wq, bq, q_ptr);
    proj_kernel<true><<<pgrid, 256>>>(K, Wk, bk, k_ptr);
    proj_kernel<true><<<pgrid, 256>>>(V, Wv, bv, v_ptr);

    logits_kernel<<<dim3(S / 64, S / 64, B * H), 256>>>(weights);
    softmax_kernel<<<B * H * S, 256>>>(weights);
    attnv_kernel<<<dim3(S / 64, B * H), 256>>>(weights);

    proj_kernel<false><<<pgrid, 256>>>(attn_ptr, Wo, bo, out);
}

// round 2
// speedup vs baseline: 1.0994x; 1.0994x over previous
#include <cuda_runtime.h>
#include <math.h>

static constexpr int B  = 2;
static constexpr int S  = 2048;
static constexpr int DM = 1024;
static constexpr int H  = 16;
static constexpr int D  = 64;
static constexpr int MTOK = B * S;   // 4096

__device__ float g_q[B * H * S * D];
__device__ float g_k[B * H * S * D];
__device__ float g_v[B * H * S * D];
__device__ float g_attn[B * S * DM];

// ---------------------------------------------------------------------------
// Projection GEMM: out = X[MTOK, DM] @ W[DM, DM] + bias
// 128x128 tile, 8x8 microtile, vectorized smem access.
// ---------------------------------------------------------------------------
template <bool SPLIT>
__global__ __launch_bounds__(256, 2) void proj_kernel(
    const float* __restrict__ X, const float* __restrict__ W,
    const float* __restrict__ bias, float* __restrict__ out)
{
    constexpr int BM = 128, BN = 128, BK = 16;
    __shared__ float As[BK][BM + 4];   // [k][m], +4 keeps 16B alignment
    __shared__ float Bs[BK][BN + 4];

    const int tid = threadIdx.x;
    const int m0 = blockIdx.y * BM;
    const int n0 = blockIdx.x * BN;
    const int ty = tid >> 4, tx = tid & 15;

    float acc[8][8] = {};

    for (int k0 = 0; k0 < DM; k0 += BK) {
        #pragma unroll
        for (int t = 0; t < 2; t++) {               // A: 128 rows x 16 k
            const int idx = tid + t * 256;
            const int row = idx >> 2, kq = idx & 3;
            const float4 v = *(const float4*)(X + (size_t)(m0 + row) * DM + k0 + kq * 4);
            As[kq * 4 + 0][row] = v.x;
            As[kq * 4 + 1][row] = v.y;
            As[kq * 4 + 2][row] = v.z;
            As[kq * 4 + 3][row] = v.w;
        }
        #pragma unroll
        for (int t = 0; t < 2; t++) {               // B: 16 k x 128 n
            const int idx = tid + t * 256;
            const int kk = idx >> 5, nq = idx & 31;
            *(float4*)&Bs[kk][nq * 4] =
                *(const float4*)(W + (size_t)(k0 + kk) * DM + n0 + nq * 4);
        }
        __syncthreads();

        #pragma unroll
        for (int kk = 0; kk < BK; kk++) {
            float a[8], b[8];
            *(float4*)&a[0] = *(const float4*)&As[kk][ty * 8];
            *(float4*)&a[4] = *(const float4*)&As[kk][ty * 8 + 4];
            *(float4*)&b[0] = *(const float4*)&Bs[kk][tx * 8];
            *(float4*)&b[4] = *(const float4*)&Bs[kk][tx * 8 + 4];
            #pragma unroll
            for (int i = 0; i < 8; i++)
                #pragma unroll
                for (int j = 0; j < 8; j++)
                    acc[i][j] = fmaf(a[i], b[j], acc[i][j]);
        }
        __syncthreads();
    }

    #pragma unroll
    for (int i = 0; i < 8; i++) {
        const int row = m0 + ty * 8 + i;
        const int bb = row / S, s = row % S;
        #pragma unroll
        for (int jq = 0; jq < 2; jq++) {
            const int col = n0 + tx * 8 + jq * 4;
            float4 v;
            v.x = acc[i][jq * 4 + 0] + __ldg(&bias[col + 0]);
            v.y = acc[i][jq * 4 + 1] + __ldg(&bias[col + 1]);
            v.z = acc[i][jq * 4 + 2] + __ldg(&bias[col + 2]);
            v.w = acc[i][jq * 4 + 3] + __ldg(&bias[col + 3]);
            if (SPLIT) {
                const int h = col / D, d = col % D;
                *(float4*)&out[(((size_t)(bb * H + h)) * S + s) * D + d] = v;
            } else {
                *(float4*)&out[(size_t)row * DM + col] = v;
            }
        }
    }
}

// ---------------------------------------------------------------------------
// Logits: L[bh,i,j] = dot(q[bh,i,:], k[bh,j,:]) * 0.125
// 128x128 tile, 8x8 microtile, K = 64.
// ---------------------------------------------------------------------------
__global__ __launch_bounds__(256, 2) void logits_kernel(float* __restrict__ Wout)
{
    constexpr int BM = 128, BN = 128, BK = 16;
    __shared__ float Qs[BK][BM + 4];
    __shared__ float Ks[BK][BN + 4];

    const int bh = blockIdx.z;
    const int i0 = blockIdx.y * BM;
    const int j0 = blockIdx.x * BN;
    const float* qb = g_q + (size_t)bh * S * D;
    const float* kb = g_k + (size_t)bh * S * D;
    const int tid = threadIdx.x;
    const int ty = tid >> 4, tx = tid & 15;

    float acc[8][8] = {};

    for (int k0 = 0; k0 < D; k0 += BK) {
        #pragma unroll
        for (int t = 0; t < 2; t++) {
            const int idx = tid + t * 256;
            const int row = idx >> 2, kq = idx & 3;
            const float4 v = *(const float4*)(qb + (size_t)(i0 + row) * D + k0 + kq * 4);
            Qs[kq * 4 + 0][row] = v.x;
            Qs[kq * 4 + 1][row] = v.y;
            Qs[kq * 4 + 2][row] = v.z;
            Qs[kq * 4 + 3][row] = v.w;
            const float4 w = *(const float4*)(kb + (size_t)(j0 + row) * D + k0 + kq * 4);
            Ks[kq * 4 + 0][row] = w.x;
            Ks[kq * 4 + 1][row] = w.y;
            Ks[kq * 4 + 2][row] = w.z;
            Ks[kq * 4 + 3][row] = w.w;
        }
        __syncthreads();

        #pragma unroll
        for (int kk = 0; kk < BK; kk++) {
            float a[8], b[8];
            *(float4*)&a[0] = *(const float4*)&Qs[kk][ty * 8];
            *(float4*)&a[4] = *(const float4*)&Qs[kk][ty * 8 + 4];
            *(float4*)&b[0] = *(const float4*)&Ks[kk][tx * 8];
            *(float4*)&b[4] = *(const float4*)&Ks[kk][tx * 8 + 4];
            #pragma unroll
            for (int i = 0; i < 8; i++)
                #pragma unroll
                for (int j = 0; j < 8; j++)
                    acc[i][j] = fmaf(a[i], b[j], acc[i][j]);
        }
        __syncthreads();
    }

    float* outb = Wout + (size_t)bh * S * S;
    #pragma unroll
    for (int i = 0; i < 8; i++) {
        const int row = i0 + ty * 8 + i;
        #pragma unroll
        for (int jq = 0; jq < 2; jq++) {
            const int col = j0 + tx * 8 + jq * 4;
            float4 v;
            v.x = acc[i][jq * 4 + 0] * 0.125f;
            v.y = acc[i][jq * 4 + 1] * 0.125f;
            v.z = acc[i][jq * 4 + 2] * 0.125f;
            v.w = acc[i][jq * 4 + 3] * 0.125f;
            *(float4*)&outb[(size_t)row * S + col] = v;
        }
    }
}

// ---------------------------------------------------------------------------
// Row softmax in place, float4 + shuffle reductions.
// ---------------------------------------------------------------------------
__global__ __launch_bounds__(256) void softmax_kernel(float* __restrict__ Wt)
{
    __shared__ float red[8];
    float* p = Wt + (size_t)blockIdx.x * S;
    const int tid = threadIdx.x;
    const int lane = tid & 31, wid = tid >> 5;

    float4 v0 = *(float4*)(p + tid * 8);
    float4 v1 = *(float4*)(p + tid * 8 + 4);

    float m = fmaxf(fmaxf(fmaxf(v0.x, v0.y), fmaxf(v0.z, v0.w)),
                    fmaxf(fmaxf(v1.x, v1.y), fmaxf(v1.z, v1.w)));
    #pragma unroll
    for (int off = 16; off > 0; off >>= 1)
        m = fmaxf(m, __shfl_xor_sync(0xffffffffu, m, off));
    if (lane == 0) red[wid] = m;
    __syncthreads();
    m = red[0];
    #pragma unroll
    for (int w = 1; w < 8; w++) m = fmaxf(m, red[w]);
    __syncthreads();

    v0.x = __expf(v0.x - m); v0.y = __expf(v0.y - m);
    v0.z = __expf(v0.z - m); v0.w = __expf(v0.w - m);
    v1.x = __expf(v1.x - m); v1.y = __expf(v1.y - m);
    v1.z = __expf(v1.z - m); v1.w = __expf(v1.w - m);
    float sum = v0.x + v0.y + v0.z + v0.w + v1.x + v1.y + v1.z + v1.w;
    #pragma unroll
    for (int off = 16; off > 0; off >>= 1)
        sum += __shfl_xor_sync(0xffffffffu, sum, off);
    if (lane == 0) red[wid] = sum;
    __syncthreads();
    sum = red[0];
    #pragma unroll
    for (int w = 1; w < 8; w++) sum += red[w];
    const float inv = 1.0f / sum;

    v0.x *= inv; v0.y *= inv; v0.z *= inv; v0.w *= inv;
    v1.x *= inv; v1.y *= inv; v1.z *= inv; v1.w *= inv;
    *(float4*)(p + tid * 8)     = v0;
    *(float4*)(p + tid * 8 + 4) = v1;
}

// ---------------------------------------------------------------------------
// attn = weights[bh,S,S] @ v[bh,S,D] -> merged (B,S,DM)
// 128x64 tile, 4x8 microtile.
// ---------------------------------------------------------------------------
__global__ __launch_bounds__(256, 2) void attnv_kernel(const float* __restrict__ Wt)
{
    constexpr int BM = 128, BN = 64, BK = 16;
    __shared__ float Ws[BK][BM + 4];
    __shared__ float Vs[BK][BN + 4];

    const int bh = blockIdx.y;
    const int m0 = blockIdx.x * BM;
    const float* wb = Wt  + (size_t)bh * S * S;
    const float* vb = g_v + (size_t)bh * S * D;
    const int bb = bh / H, h = bh % H;
    const int tid = threadIdx.x;
    const int ty = tid >> 3, tx = tid & 7;    // 32 x 8 threads -> 4x8 micro

    float acc[4][8] = {};

    for (int k0 = 0; k0 < S; k0 += BK) {
        #pragma unroll
        for (int t = 0; t < 2; t++) {               // W: 128 rows x 16 k
            const int idx = tid + t * 256;
            const int row = idx >> 2, kq = idx & 3;
            const float4 v = *(const float4*)(wb + (size_t)(m0 + row) * S + k0 + kq * 4);
            Ws[kq * 4 + 0][row] = v.x;
            Ws[kq * 4 + 1][row] = v.y;
            Ws[kq * 4 + 2][row] = v.z;
            Ws[kq * 4 + 3][row] = v.w;
        }
        {                                           // V: 16 k x 64 d
            const int kk = tid >> 4, dq = tid & 15;
            *(float4*)&Vs[kk][dq * 4] =
                *(const float4*)(vb + (size_t)(k0 + kk) * D + dq * 4);
        }
        __syncthreads();

        #pragma unroll
        for (int kk = 0; kk < BK; kk++) {
            float a[4], b[8];
            *(float4*)&a[0] = *(const float4*)&Ws[kk][ty * 4];
            *(float4*)&b[0] = *(const float4*)&Vs[kk][tx * 8];
            *(float4*)&b[4] = *(const float4*)&Vs[kk][tx * 8 + 4];
            #pragma unroll
            for (int i = 0; i < 4; i++)
                #pragma unroll
                for (int j = 0; j < 8; j++)
                    acc[i][j] = fmaf(a[i], b[j], acc[i][j]);
        }
        __syncthreads();
    }

    #pragma unroll
    for (int i = 0; i < 4; i++) {
        const int s = m0 + ty * 4 + i;
        float* dst = g_attn + ((size_t)(bb * S + s)) * DM + h * D + tx * 8;
        *(float4*)(dst)     = make_float4(acc[i][0], acc[i][1], acc[i][2], acc[i][3]);
        *(float4*)(dst + 4) = make_float4(acc[i][4], acc[i][5], acc[i][6], acc[i][7]);
    }
}

// ---------------------------------------------------------------------------
extern "C" void kernel_launch(void* const* d_in, const int* in_sizes, int n_in,
                              void* d_out, int out_size)
{
    const float* Q  = (const float*)d_in[0];
    const float* K  = (const float*)d_in[1];
    const float* V  = (const float*)d_in[2];
    const float* Wq = (const float*)d_in[3];
    const float* bq = (const float*)d_in[4];
    const float* Wk = (const float*)d_in[5];
    const float* bk = (const float*)d_in[6];
    const float* Wv = (const float*)d_in[7];
    const float* bv = (const float*)d_in[8];
    const float* Wo = (const float*)d_in[9];
    const float* bo = (const float*)d_in[10];

    float* out     = (float*)d_out;
    float* weights = out + (size_t)B * S * DM;

    float *q_ptr, *k_ptr, *v_ptr, *attn_ptr;
    cudaGetSymbolAddress((void**)&q_ptr, g_q);
    cudaGetSymbolAddress((void**)&k_ptr, g_k);
    cudaGetSymbolAddress((void**)&v_ptr, g_v);
    cudaGetSymbolAddress((void**)&attn_ptr, g_attn);

    dim3 pgrid(DM / 128, MTOK / 128);   // (8, 32)

    proj_kernel<true><<<pgrid, 256>>>(Q, Wq, bq, q_ptr);
    proj_kernel<true><<<pgrid, 256>>>(K, Wk, bk, k_ptr);
    proj_kernel<true><<<pgrid, 256>>>(V, Wv, bv, v_ptr);

    logits_kernel<<<dim3(S / 128, S / 128, B * H), 256>>>(weights);
    softmax_kernel<<<B * H * S, 256>>>(weights);
    attnv_kernel<<<dim3(S / 128, B * H), 256>>>(weights);

    proj_kernel<false><<<pgrid, 256>>>(attn_ptr, Wo, bo, out);
}

// round 3
// speedup vs baseline: 1.3702x; 1.2462x over previous
#include <cuda_runtime.h>
#include <math.h>
#include <stdint.h>

static constexpr int B  = 2;
static constexpr int S  = 2048;
static constexpr int DM = 1024;
static constexpr int H  = 16;
static constexpr int D  = 64;
static constexpr int MTOK = B * S;   // 4096

__device__ float g_q[B * H * S * D];
__device__ float g_k[B * H * S * D];
__device__ float g_v[B * H * S * D];
__device__ float g_attn[B * S * DM];

// ---------------------------------------------------------------------------
// TF32 helpers: 3xTF32 split (hi = tf32-truncated, lo = residual)
// ---------------------------------------------------------------------------
__device__ __forceinline__ void split_tf32(float x, float& hi, float& lo) {
    hi = __uint_as_float(__float_as_uint(x) & 0xffffe000u);
    lo = x - hi;
}

__device__ __forceinline__ void mma8(float* c, const float* a, const float* b) {
    asm volatile(
        "mma.sync.aligned.m16n8k8.row.col.f32.tf32.tf32.f32 "
        "{%0,%1,%2,%3}, {%4,%5,%6,%7}, {%8,%9}, {%0,%1,%2,%3};\n"
        : "+f"(c[0]), "+f"(c[1]), "+f"(c[2]), "+f"(c[3])
        : "r"(__float_as_uint(a[0])), "r"(__float_as_uint(a[1])),
          "r"(__float_as_uint(a[2])), "r"(__float_as_uint(a[3])),
          "r"(__float_as_uint(b[0])), "r"(__float_as_uint(b[1])));
}

// ---------------------------------------------------------------------------
// Projection GEMM (tensor cores): out = X[MTOK,DM] @ W[DM,DM] + bias
// 128x128 CTA tile, 8 warps (2x4), warp tile 64x32, BK=32.
// ---------------------------------------------------------------------------
template <bool SPLIT>
__global__ __launch_bounds__(256) void proj_tc(
    const float* __restrict__ X, const float* __restrict__ W,
    const float* __restrict__ bias, float* __restrict__ out)
{
    constexpr int BM = 128, BN = 128, BK = 32;
    __shared__ float As[BK][BM + 4];   // [k][m]
    __shared__ float Bs[BK][BN + 4];   // [k][n]

    const int tid  = threadIdx.x;
    const int warp = tid >> 5, lane = tid & 31;
    const int g    = lane >> 2, tig = lane & 3;
    const int warp_m = (warp >> 2) * 64;
    const int warp_n = (warp & 3) * 32;
    const int m0 = blockIdx.y * BM;
    const int n0 = blockIdx.x * BN;

    float acc[4][4][4] = {};

    for (int k0 = 0; k0 < DM; k0 += BK) {
        #pragma unroll
        for (int t = 0; t < 4; t++) {              // A: 128 rows x 32 k
            const int e = tid + t * 256;
            const int row = e >> 3, kq = e & 7;
            const float4 v = *(const float4*)(X + (size_t)(m0 + row) * DM + k0 + kq * 4);
            As[kq * 4 + 0][row] = v.x;
            As[kq * 4 + 1][row] = v.y;
            As[kq * 4 + 2][row] = v.z;
            As[kq * 4 + 3][row] = v.w;
        }
        #pragma unroll
        for (int t = 0; t < 4; t++) {              // B: 32 k x 128 n
            const int e = tid + t * 256;
            const int kk = e >> 5, nq = e & 31;
            *(float4*)&Bs[kk][nq * 4] =
                *(const float4*)(W + (size_t)(k0 + kk) * DM + n0 + nq * 4);
        }
        __syncthreads();

        #pragma unroll
        for (int ks = 0; ks < BK / 8; ks++) {
            const int kb = ks * 8;
            float ah[4][4], al[4][4], bh[4][2], bl[4][2];
            #pragma unroll
            for (int mi = 0; mi < 4; mi++) {
                const int m = warp_m + mi * 16;
                split_tf32(As[kb + tig    ][m + g    ], ah[mi][0], al[mi][0]);
                split_tf32(As[kb + tig    ][m + g + 8], ah[mi][1], al[mi][1]);
                split_tf32(As[kb + tig + 4][m + g    ], ah[mi][2], al[mi][2]);
                split_tf32(As[kb + tig + 4][m + g + 8], ah[mi][3], al[mi][3]);
            }
            #pragma unroll
            for (int nj = 0; nj < 4; nj++) {
                const int n = warp_n + nj * 8;
                split_tf32(Bs[kb + tig    ][n + g], bh[nj][0], bl[nj][0]);
                split_tf32(Bs[kb + tig + 4][n + g], bh[nj][1], bl[nj][1]);
            }
            #pragma unroll
            for (int mi = 0; mi < 4; mi++)
                #pragma unroll
                for (int nj = 0; nj < 4; nj++) {
                    mma8(acc[mi][nj], ah[mi], bh[nj]);
                    mma8(acc[mi][nj], ah[mi], bl[nj]);
                    mma8(acc[mi][nj], al[mi], bh[nj]);
                }
        }
        __syncthreads();
    }

    #pragma unroll
    for (int mi = 0; mi < 4; mi++) {
        #pragma unroll
        for (int nj = 0; nj < 4; nj++) {
            const int c  = n0 + warp_n + nj * 8 + tig * 2;
            const int r0 = m0 + warp_m + mi * 16 + g;
            const int r1 = r0 + 8;
            float2 w0, w1;
            w0.x = acc[mi][nj][0] + __ldg(&bias[c]);
            w0.y = acc[mi][nj][1] + __ldg(&bias[c + 1]);
            w1.x = acc[mi][nj][2] + __ldg(&bias[c]);
            w1.y = acc[mi][nj][3] + __ldg(&bias[c + 1]);
            if (SPLIT) {
                const int h = c / D, d = c % D;
                const int b0r = r0 / S, s0r = r0 % S;
                const int b1r = r1 / S, s1r = r1 % S;
                *(float2*)&out[(((size_t)(b0r * H + h)) * S + s0r) * D + d] = w0;
                *(float2*)&out[(((size_t)(b1r * H + h)) * S + s1r) * D + d] = w1;
            } else {
                *(float2*)&out[(size_t)r0 * DM + c] = w0;
                *(float2*)&out[(size_t)r1 * DM + c] = w1;
            }
        }
    }
}

// ---------------------------------------------------------------------------
// Logits (tensor cores): L[bh,i,j] = dot(q[i,:], k[j,:]) * 0.125
// ---------------------------------------------------------------------------
__global__ __launch_bounds__(256) void logits_tc(float* __restrict__ Wout)
{
    constexpr int BM = 128, BN = 128, BK = 32;
    __shared__ float As[BK][BM + 4];   // [d][i]
    __shared__ float Bs[BK][BN + 4];   // [d][j]

    const int tid  = threadIdx.x;
    const int warp = tid >> 5, lane = tid & 31;
    const int g    = lane >> 2, tig = lane & 3;
    const int warp_m = (warp >> 2) * 64;
    const int warp_n = (warp & 3) * 32;
    const int bh = blockIdx.z;
    const int i0 = blockIdx.y * BM;
    const int j0 = blockIdx.x * BN;
    const float* qb = g_q + (size_t)bh * S * D;
    const float* kb = g_k + (size_t)bh * S * D;

    float acc[4][4][4] = {};

    for (int d0 = 0; d0 < D; d0 += BK) {
        #pragma unroll
        for (int t = 0; t < 4; t++) {
            const int e = tid + t * 256;
            const int row = e >> 3, kq = e & 7;
            const float4 v = *(const float4*)(qb + (size_t)(i0 + row) * D + d0 + kq * 4);
            As[kq * 4 + 0][row] = v.x;
            As[kq * 4 + 1][row] = v.y;
            As[kq * 4 + 2][row] = v.z;
            As[kq * 4 + 3][row] = v.w;
            const float4 w = *(const float4*)(kb + (size_t)(j0 + row) * D + d0 + kq * 4);
            Bs[kq * 4 + 0][row] = w.x;
            Bs[kq * 4 + 1][row] = w.y;
            Bs[kq * 4 + 2][row] = w.z;
            Bs[kq * 4 + 3][row] = w.w;
        }
        __syncthreads();

        #pragma unroll
        for (int ks = 0; ks < BK / 8; ks++) {
            const int kb2 = ks * 8;
            float ah[4][4], al[4][4], bh[4][2], bl[4][2];
            #pragma unroll
            for (int mi = 0; mi < 4; mi++) {
                const int m = warp_m + mi * 16;
                split_tf32(As[kb2 + tig    ][m + g    ], ah[mi][0], al[mi][0]);
                split_tf32(As[kb2 + tig    ][m + g + 8], ah[mi][1], al[mi][1]);
                split_tf32(As[kb2 + tig + 4][m + g    ], ah[mi][2], al[mi][2]);
                split_tf32(As[kb2 + tig + 4][m + g + 8], ah[mi][3], al[mi][3]);
            }
            #pragma unroll
            for (int nj = 0; nj < 4; nj++) {
                const int n = warp_n + nj * 8;
                split_tf32(Bs[kb2 + tig    ][n + g], bh[nj][0], bl[nj][0]);
                split_tf32(Bs[kb2 + tig + 4][n + g], bh[nj][1], bl[nj][1]);
            }
            #pragma unroll
            for (int mi = 0; mi < 4; mi++)
                #pragma unroll
                for (int nj = 0; nj < 4; nj++) {
                    mma8(acc[mi][nj], ah[mi], bh[nj]);
                    mma8(acc[mi][nj], ah[mi], bl[nj]);
                    mma8(acc[mi][nj], al[mi], bh[nj]);
                }
        }
        __syncthreads();
    }

    float* outb = Wout + (size_t)bh * S * S;
    #pragma unroll
    for (int mi = 0; mi < 4; mi++) {
        #pragma unroll
        for (int nj = 0; nj < 4; nj++) {
            const int c  = j0 + warp_n + nj * 8 + tig * 2;
            const int r0 = i0 + warp_m + mi * 16 + g;
            const int r1 = r0 + 8;
            float2 w0 = make_float2(acc[mi][nj][0] * 0.125f, acc[mi][nj][1] * 0.125f);
            float2 w1 = make_float2(acc[mi][nj][2] * 0.125f, acc[mi][nj][3] * 0.125f);
            *(float2*)&outb[(size_t)r0 * S + c] = w0;
            *(float2*)&outb[(size_t)r1 * S + c] = w1;
        }
    }
}

// ---------------------------------------------------------------------------
// Row softmax in place.
// ---------------------------------------------------------------------------
__global__ __launch_bounds__(256) void softmax_kernel(float* __restrict__ Wt)
{
    __shared__ float red[8];
    float* p = Wt + (size_t)blockIdx.x * S;
    const int tid = threadIdx.x;
    const int lane = tid & 31, wid = tid >> 5;

    float4 v0 = *(float4*)(p + tid * 8);
    float4 v1 = *(float4*)(p + tid * 8 + 4);

    float m = fmaxf(fmaxf(fmaxf(v0.x, v0.y), fmaxf(v0.z, v0.w)),
                    fmaxf(fmaxf(v1.x, v1.y), fmaxf(v1.z, v1.w)));
    #pragma unroll
    for (int off = 16; off > 0; off >>= 1)
        m = fmaxf(m, __shfl_xor_sync(0xffffffffu, m, off));
    if (lane == 0) red[wid] = m;
    __syncthreads();
    m = red[0];
    #pragma unroll
    for (int w = 1; w < 8; w++) m = fmaxf(m, red[w]);
    __syncthreads();

    v0.x = __expf(v0.x - m); v0.y = __expf(v0.y - m);
    v0.z = __expf(v0.z - m); v0.w = __expf(v0.w - m);
    v1.x = __expf(v1.x - m); v1.y = __expf(v1.y - m);
    v1.z = __expf(v1.z - m); v1.w = __expf(v1.w - m);
    float sum = v0.x + v0.y + v0.z + v0.w + v1.x + v1.y + v1.z + v1.w;
    #pragma unroll
    for (int off = 16; off > 0; off >>= 1)
        sum += __shfl_xor_sync(0xffffffffu, sum, off);
    if (lane == 0) red[wid] = sum;
    __syncthreads();
    sum = red[0];
    #pragma unroll
    for (int w = 1; w < 8; w++) sum += red[w];
    const float inv = 1.0f / sum;

    v0.x *= inv; v0.y *= inv; v0.z *= inv; v0.w *= inv;
    v1.x *= inv; v1.y *= inv; v1.z *= inv; v1.w *= inv;
    *(float4*)(p + tid * 8)     = v0;
    *(float4*)(p + tid * 8 + 4) = v1;
}

// ---------------------------------------------------------------------------
// attn = weights[bh,S,S] @ v[bh,S,D] -> merged (B,S,DM)  (tensor cores)
// 128x64 tile, 8 warps (4x2), warp tile 32x32, BK=32.
// ---------------------------------------------------------------------------
__global__ __launch_bounds__(256) void attnv_tc(const float* __restrict__ Wt)
{
    constexpr int BM = 128, BN = 64, BK = 32;
    __shared__ float As[BK][BM + 4];   // [j][s]
    __shared__ float Bs[BK][BN + 4];   // [j][d]

    const int tid  = threadIdx.x;
    const int warp = tid >> 5, lane = tid & 31;
    const int g    = lane >> 2, tig = lane & 3;
    const int warp_m = (warp >> 1) * 32;
    const int warp_n = (warp & 1) * 32;
    const int bh = blockIdx.y;
    const int m0 = blockIdx.x * BM;
    const float* wb = Wt  + (size_t)bh * S * S;
    const float* vb = g_v + (size_t)bh * S * D;
    const int bb = bh / H, h = bh % H;

    float acc[2][4][4] = {};

    for (int k0 = 0; k0 < S; k0 += BK) {
        #pragma unroll
        for (int t = 0; t < 4; t++) {              // W: 128 rows x 32 j
            const int e = tid + t * 256;
            const int row = e >> 3, kq = e & 7;
            const float4 v = *(const float4*)(wb + (size_t)(m0 + row) * S + k0 + kq * 4);
            As[kq * 4 + 0][row] = v.x;
            As[kq * 4 + 1][row] = v.y;
            As[kq * 4 + 2][row] = v.z;
            As[kq * 4 + 3][row] = v.w;
        }
        #pragma unroll
        for (int t = 0; t < 2; t++) {              // V: 32 j x 64 d
            const int e = tid + t * 256;
            const int kk = e >> 4, dq = e & 15;
            *(float4*)&Bs[kk][dq * 4] =
                *(const float4*)(vb + (size_t)(k0 + kk) * D + dq * 4);
        }
        __syncthreads();

        #pragma unroll
        for (int ks = 0; ks < BK / 8; ks++) {
            const int kb2 = ks * 8;
            float ah[2][4], al[2][4], bh[4][2], bl[4][2];
            #pragma unroll
            for (int mi = 0; mi < 2; mi++) {
                const int m = warp_m + mi * 16;
                split_tf32(As[kb2 + tig    ][m + g    ], ah[mi][0], al[mi][0]);
                split_tf32(As[kb2 + tig    ][m + g + 8], ah[mi][1], al[mi][1]);
                split_tf32(As[kb2 + tig + 4][m + g    ], ah[mi][2], al[mi][2]);
                split_tf32(As[kb2 + tig + 4][m + g + 8], ah[mi][3], al[mi][3]);
            }
            #pragma unroll
            for (int nj = 0; nj < 4; nj++) {
                const int n = warp_n + nj * 8;
                split_tf32(Bs[kb2 + tig    ][n + g], bh[nj][0], bl[nj][0]);
                split_tf32(Bs[kb2 + tig + 4][n + g], bh[nj][1], bl[nj][1]);
            }
            #pragma unroll
            for (int mi = 0; mi < 2; mi++)
                #pragma unroll
                for (int nj = 0; nj < 4; nj++) {
                    mma8(acc[mi][nj], ah[mi], bh[nj]);
                    mma8(acc[mi][nj], ah[mi], bl[nj]);
                    mma8(acc[mi][nj], al[mi], bh[nj]);
                }
        }
        __syncthreads();
    }

    #pragma unroll
    for (int mi = 0; mi < 2; mi++) {
        #pragma unroll
        for (int nj = 0; nj < 4; nj++) {
            const int d  = warp_n + nj * 8 + tig * 2;
            const int s0 = m0 + warp_m + mi * 16 + g;
            const int s1 = s0 + 8;
            float2 w0 = make_float2(acc[mi][nj][0], acc[mi][nj][1]);
            float2 w1 = make_float2(acc[mi][nj][2], acc[mi][nj][3]);
            *(float2*)&g_attn[((size_t)(bb * S + s0)) * DM + h * D + d] = w0;
            *(float2*)&g_attn[((size_t)(bb * S + s1)) * DM + h * D + d] = w1;
        }
    }
}

// ---------------------------------------------------------------------------
extern "C" void kernel_launch(void* const* d_in, const int* in_sizes, int n_in,
                              void* d_out, int out_size)
{
    const float* Q  = (const float*)d_in[0];
    const float* K  = (const float*)d_in[1];
    const float* V  = (const float*)d_in[2];
    const float* Wq = (const float*)d_in[3];
    const float* bq = (const float*)d_in[4];
    const float* Wk = (const float*)d_in[5];
    const float* bk = (const float*)d_in[6];
    const float* Wv = (const float*)d_in[7];
    const float* bv = (const float*)d_in[8];
    const float* Wo = (const float*)d_in[9];
    const float* bo = (const float*)d_in[10];

    float* out     = (float*)d_out;
    float* weights = out + (size_t)B * S * DM;

    float *q_ptr, *k_ptr, *v_ptr, *attn_ptr;
    cudaGetSymbolAddress((void**)&q_ptr, g_q);
    cudaGetSymbolAddress((void**)&k_ptr, g_k);
    cudaGetSymbolAddress((void**)&v_ptr, g_v);
    cudaGetSymbolAddress((void**)&attn_ptr, g_attn);

    dim3 pgrid(DM / 128, MTOK / 128);   // (8, 32)

    proj_tc<true><<<pgrid, 256>>>(Q, Wq, bq, q_ptr);
    proj_tc<true><<<pgrid, 256>>>(K, Wk, bk, k_ptr);
    proj_tc<true><<<pgrid, 256>>>(V, Wv, bv, v_ptr);

    logits_tc<<<dim3(S / 128, S / 128, B * H), 256>>>(weights);
    softmax_kernel<<<B * H * S, 256>>>(weights);
    attnv_tc<<<dim3(S / 128, B * H), 256>>>(weights);

    proj_tc<false><<<pgrid, 256>>>(attn_ptr, Wo, bo, out);
}

// round 4
// speedup vs baseline: 1.6768x; 1.2238x over previous
#include <cuda_runtime.h>
#include <cuda_bf16.h>
#include <math.h>
#include <stdint.h>

static constexpr int B  = 2;
static constexpr int S  = 2048;
static constexpr int DM = 1024;
static constexpr int H  = 16;
static constexpr int D  = 64;
static constexpr int MTOK = B * S;   // 4096

static constexpr int BK = 16;        // fp32 k per mainloop iter
static constexpr int PW = 20;        // words per smem row (16 + 4 pad)

__device__ float g_q[B * H * S * D];
__device__ float g_k[B * H * S * D];
__device__ float g_v[B * H * S * D];
__device__ float g_attn[B * S * DM];

// ---------------------------------------------------------------------------
// Split helpers: one 32-bit word = (lo_bf16 << 16) | hi_bf16 for one fp32.
// ---------------------------------------------------------------------------
__device__ __forceinline__ unsigned pack2(float x) {
    __nv_bfloat16 h = __float2bfloat16(x);
    __nv_bfloat16 l = __float2bfloat16(x - __bfloat162float(h));
    return ((unsigned)__bfloat16_as_ushort(l) << 16) |
           (unsigned)__bfloat16_as_ushort(h);
}
__device__ __forceinline__ uint4 pack4(float4 v) {
    return make_uint4(pack2(v.x), pack2(v.y), pack2(v.z), pack2(v.w));
}

// mma.sync m16n8k16 bf16 with fp32 accumulate
__device__ __forceinline__ void mma16(float* c, const unsigned* a,
                                      unsigned b0, unsigned b1) {
    asm volatile(
        "mma.sync.aligned.m16n8k16.row.col.f32.bf16.bf16.f32 "
        "{%0,%1,%2,%3}, {%4,%5,%6,%7}, {%8,%9}, {%0,%1,%2,%3};\n"
        : "+f"(c[0]), "+f"(c[1]), "+f"(c[2]), "+f"(c[3])
        : "r"(a[0]), "r"(a[1]), "r"(a[2]), "r"(a[3]), "r"(b0), "r"(b1));
}

// One k16 step over the doubled-k (hi,lo) layout: acc += A_split * B_split
__device__ __forceinline__ void mma_step(float* acc, const unsigned* af,
                                         unsigned b0, unsigned b1) {
    unsigned bhh0 = __byte_perm(b0, b0, 0x1010);
    unsigned bhh1 = __byte_perm(b1, b1, 0x1010);
    unsigned bll0 = __byte_perm(b0, b0, 0x3232);
    unsigned bll1 = __byte_perm(b1, b1, 0x3232);
    mma16(acc, af, bhh0, bhh1);
    mma16(acc, af, bll0, bll1);
}

// ---------------------------------------------------------------------------
// Projection GEMM: out = X[MTOK,DM] @ W[DM,DM] + bias (split-bf16 TC)
// 128x128 CTA, 8 warps (2x4), warp tile 64x32, double-buffered.
// ---------------------------------------------------------------------------
template <bool SPLIT>
__global__ __launch_bounds__(256, 2) void proj_tc(
    const float* __restrict__ X, const float* __restrict__ W,
    const float* __restrict__ bias, float* __restrict__ out)
{
    __shared__ unsigned As[2][128 * PW];
    __shared__ unsigned Bs[2][128 * PW];

    const int tid  = threadIdx.x;
    const int warp = tid >> 5, lane = tid & 31;
    const int g    = lane >> 2, tig = lane & 3;
    const int warp_m = (warp >> 2) * 64;
    const int warp_n = (warp & 3) * 32;
    const int m0 = blockIdx.y * 128;
    const int n0 = blockIdx.x * 128;

    const int a_row = tid >> 2, a_kq = (tid & 3) * 4;       // +64 rows for t=1
    const int b_k   = tid >> 5, b_nq = (tid & 31) * 4;      // +8 k for t=1

    float acc[4][4][4] = {};
    float4 sa[2], sb[2];

    auto load_stage = [&](int k0) {
        sa[0] = *(const float4*)(X + (size_t)(m0 + a_row)      * DM + k0 + a_kq);
        sa[1] = *(const float4*)(X + (size_t)(m0 + a_row + 64) * DM + k0 + a_kq);
        sb[0] = *(const float4*)(W + (size_t)(k0 + b_k)     * DM + n0 + b_nq);
        sb[1] = *(const float4*)(W + (size_t)(k0 + b_k + 8) * DM + n0 + b_nq);
    };
    auto store_stage = [&](int buf) {
        *(uint4*)&As[buf][(a_row)      * PW + a_kq] = pack4(sa[0]);
        *(uint4*)&As[buf][(a_row + 64) * PW + a_kq] = pack4(sa[1]);
        uint4 p0 = pack4(sb[0]), p1 = pack4(sb[1]);
        Bs[buf][(b_nq + 0) * PW + b_k] = p0.x;
        Bs[buf][(b_nq + 1) * PW + b_k] = p0.y;
        Bs[buf][(b_nq + 2) * PW + b_k] = p0.z;
        Bs[buf][(b_nq + 3) * PW + b_k] = p0.w;
        Bs[buf][(b_nq + 0) * PW + b_k + 8] = p1.x;
        Bs[buf][(b_nq + 1) * PW + b_k + 8] = p1.y;
        Bs[buf][(b_nq + 2) * PW + b_k + 8] = p1.z;
        Bs[buf][(b_nq + 3) * PW + b_k + 8] = p1.w;
    };
    auto compute = [&](int buf) {
        const unsigned* A = As[buf];
        const unsigned* Bb = Bs[buf];
        #pragma unroll
        for (int s = 0; s < 2; s++) {
            unsigned af[4][4];
            #pragma unroll
            for (int mi = 0; mi < 4; mi++) {
                const int m = warp_m + mi * 16;
                af[mi][0] = A[(m + g)     * PW + s * 8 + tig];
                af[mi][1] = A[(m + g + 8) * PW + s * 8 + tig];
                af[mi][2] = A[(m + g)     * PW + s * 8 + tig + 4];
                af[mi][3] = A[(m + g + 8) * PW + s * 8 + tig + 4];
            }
            #pragma unroll
            for (int nj = 0; nj < 4; nj++) {
                const int n = warp_n + nj * 8;
                unsigned b0 = Bb[(n + g) * PW + s * 8 + tig];
                unsigned b1 = Bb[(n + g) * PW + s * 8 + tig + 4];
                #pragma unroll
                for (int mi = 0; mi < 4; mi++)
                    mma_step(acc[mi][nj], af[mi], b0, b1);
            }
        }
    };

    const int T = DM / BK;   // 64
    load_stage(0);
    store_stage(0);
    __syncthreads();
    for (int t = 0; t < T; t++) {
        if (t + 1 < T) load_stage((t + 1) * BK);
        compute(t & 1);
        __syncthreads();
        if (t + 1 < T) {
            store_stage((t + 1) & 1);
            __syncthreads();
        }
    }

    #pragma unroll
    for (int mi = 0; mi < 4; mi++) {
        #pragma unroll
        for (int nj = 0; nj < 4; nj++) {
            const int c  = n0 + warp_n + nj * 8 + tig * 2;
            const int r0 = m0 + warp_m + mi * 16 + g;
            const int r1 = r0 + 8;
            float2 w0, w1;
            w0.x = acc[mi][nj][0] + __ldg(&bias[c]);
            w0.y = acc[mi][nj][1] + __ldg(&bias[c + 1]);
            w1.x = acc[mi][nj][2] + __ldg(&bias[c]);
            w1.y = acc[mi][nj][3] + __ldg(&bias[c + 1]);
            if (SPLIT) {
                const int h = c / D, d = c % D;
                const int b0r = r0 / S, s0r = r0 % S;
                const int b1r = r1 / S, s1r = r1 % S;
                *(float2*)&out[(((size_t)(b0r * H + h)) * S + s0r) * D + d] = w0;
                *(float2*)&out[(((size_t)(b1r * H + h)) * S + s1r) * D + d] = w1;
            } else {
                *(float2*)&out[(size_t)r0 * DM + c] = w0;
                *(float2*)&out[(size_t)r1 * DM + c] = w1;
            }
        }
    }
}

// ---------------------------------------------------------------------------
// Logits: L[bh,i,j] = dot(q[i,:], k[j,:]) * 0.125  (split-bf16 TC)
// ---------------------------------------------------------------------------
__global__ __launch_bounds__(256, 2) void logits_tc(float* __restrict__ Wout)
{
    __shared__ unsigned As[2][128 * PW];
    __shared__ unsigned Bs[2][128 * PW];

    const int tid  = threadIdx.x;
    const int warp = tid >> 5, lane = tid & 31;
    const int g    = lane >> 2, tig = lane & 3;
    const int warp_m = (warp >> 2) * 64;
    const int warp_n = (warp & 3) * 32;
    const int bh = blockIdx.z;
    const int i0 = blockIdx.y * 128;
    const int j0 = blockIdx.x * 128;
    const float* qb = g_q + (size_t)bh * S * D;
    const float* kb = g_k + (size_t)bh * S * D;

    const int a_row = tid >> 2, a_kq = (tid & 3) * 4;

    float acc[4][4][4] = {};
    float4 sa[2], sb[2];

    auto load_stage = [&](int k0) {
        sa[0] = *(const float4*)(qb + (size_t)(i0 + a_row)      * D + k0 + a_kq);
        sa[1] = *(const float4*)(qb + (size_t)(i0 + a_row + 64) * D + k0 + a_kq);
        sb[0] = *(const float4*)(kb + (size_t)(j0 + a_row)      * D + k0 + a_kq);
        sb[1] = *(const float4*)(kb + (size_t)(j0 + a_row + 64) * D + k0 + a_kq);
    };
    auto store_stage = [&](int buf) {
        *(uint4*)&As[buf][(a_row)      * PW + a_kq] = pack4(sa[0]);
        *(uint4*)&As[buf][(a_row + 64) * PW + a_kq] = pack4(sa[1]);
        *(uint4*)&Bs[buf][(a_row)      * PW + a_kq] = pack4(sb[0]);
        *(uint4*)&Bs[buf][(a_row + 64) * PW + a_kq] = pack4(sb[1]);
    };
    auto compute = [&](int buf) {
        const unsigned* A = As[buf];
        const unsigned* Bb = Bs[buf];
        #pragma unroll
        for (int s = 0; s < 2; s++) {
            unsigned af[4][4];
            #pragma unroll
            for (int mi = 0; mi < 4; mi++) {
                const int m = warp_m + mi * 16;
                af[mi][0] = A[(m + g)     * PW + s * 8 + tig];
                af[mi][1] = A[(m + g + 8) * PW + s * 8 + tig];
                af[mi][2] = A[(m + g)     * PW + s * 8 + tig + 4];
                af[mi][3] = A[(m + g + 8) * PW + s * 8 + tig + 4];
            }
            #pragma unroll
            for (int nj = 0; nj < 4; nj++) {
                const int n = warp_n + nj * 8;
                unsigned b0 = Bb[(n + g) * PW + s * 8 + tig];
                unsigned b1 = Bb[(n + g) * PW + s * 8 + tig + 4];
                #pragma unroll
                for (int mi = 0; mi < 4; mi++)
                    mma_step(acc[mi][nj], af[mi], b0, b1);
            }
        }
    };

    const int T = D / BK;   // 4
    load_stage(0);
    store_stage(0);
    __syncthreads();
    for (int t = 0; t < T; t++) {
        if (t + 1 < T) load_stage((t + 1) * BK);
        compute(t & 1);
        __syncthreads();
        if (t + 1 < T) {
            store_stage((t + 1) & 1);
            __syncthreads();
        }
    }

    float* outb = Wout + (size_t)bh * S * S;
    #pragma unroll
    for (int mi = 0; mi < 4; mi++) {
        #pragma unroll
        for (int nj = 0; nj < 4; nj++) {
            const int c  = j0 + warp_n + nj * 8 + tig * 2;
            const int r0 = i0 + warp_m + mi * 16 + g;
            const int r1 = r0 + 8;
            float2 w0 = make_float2(acc[mi][nj][0] * 0.125f, acc[mi][nj][1] * 0.125f);
            float2 w1 = make_float2(acc[mi][nj][2] * 0.125f, acc[mi][nj][3] * 0.125f);
            *(float2*)&outb[(size_t)r0 * S + c] = w0;
            *(float2*)&outb[(size_t)r1 * S + c] = w1;
        }
    }
}

// ---------------------------------------------------------------------------
// Row softmax in place.
// ---------------------------------------------------------------------------
__global__ __launch_bounds__(256) void softmax_kernel(float* __restrict__ Wt)
{
    __shared__ float red[8];
    float* p = Wt + (size_t)blockIdx.x * S;
    const int tid = threadIdx.x;
    const int lane = tid & 31, wid = tid >> 5;

    float4 v0 = *(float4*)(p + tid * 8);
    float4 v1 = *(float4*)(p + tid * 8 + 4);

    float m = fmaxf(fmaxf(fmaxf(v0.x, v0.y), fmaxf(v0.z, v0.w)),
                    fmaxf(fmaxf(v1.x, v1.y), fmaxf(v1.z, v1.w)));
    #pragma unroll
    for (int off = 16; off > 0; off >>= 1)
        m = fmaxf(m, __shfl_xor_sync(0xffffffffu, m, off));
    if (lane == 0) red[wid] = m;
    __syncthreads();
    m = red[0];
    #pragma unroll
    for (int w = 1; w < 8; w++) m = fmaxf(m, red[w]);
    __syncthreads();

    v0.x = __expf(v0.x - m); v0.y = __expf(v0.y - m);
    v0.z = __expf(v0.z - m); v0.w = __expf(v0.w - m);
    v1.x = __expf(v1.x - m); v1.y = __expf(v1.y - m);
    v1.z = __expf(v1.z - m); v1.w = __expf(v1.w - m);
    float sum = v0.x + v0.y + v0.z + v0.w + v1.x + v1.y + v1.z + v1.w;
    #pragma unroll
    for (int off = 16; off > 0; off >>= 1)
        sum += __shfl_xor_sync(0xffffffffu, sum, off);
    if (lane == 0) red[wid] = sum;
    __syncthreads();
    sum = red[0];
    #pragma unroll
    for (int w = 1; w < 8; w++) sum += red[w];
    const float inv = 1.0f / sum;

    v0.x *= inv; v0.y *= inv; v0.z *= inv; v0.w *= inv;
    v1.x *= inv; v1.y *= inv; v1.z *= inv; v1.w *= inv;
    *(float4*)(p + tid * 8)     = v0;
    *(float4*)(p + tid * 8 + 4) = v1;
}

// ---------------------------------------------------------------------------
// attn = weights[bh,S,S] @ v[bh,S,D] -> merged (B,S,DM)  (split-bf16 TC)
// 128x64 CTA, 8 warps (4x2), warp tile 32x32, double-buffered.
// ---------------------------------------------------------------------------
__global__ __launch_bounds__(256, 2) void attnv_tc(const float* __restrict__ Wt)
{
    __shared__ unsigned As[2][128 * PW];
    __shared__ unsigned Bs[2][64 * PW];

    const int tid  = threadIdx.x;
    const int warp = tid >> 5, lane = tid & 31;
    const int g    = lane >> 2, tig = lane & 3;
    const int warp_m = (warp >> 1) * 32;
    const int warp_n = (warp & 1) * 32;
    const int bh = blockIdx.y;
    const int m0 = blockIdx.x * 128;
    const float* wb = Wt  + (size_t)bh * S * S;
    const float* vb = g_v + (size_t)bh * S * D;
    const int bb = bh / H, h = bh % H;

    const int a_row = tid >> 2, a_kq = (tid & 3) * 4;
    const int b_k   = tid >> 4, b_dq = (tid & 15) * 4;

    float acc[2][4][4] = {};
    float4 sa[2], sb;

    auto load_stage = [&](int k0) {
        sa[0] = *(const float4*)(wb + (size_t)(m0 + a_row)      * S + k0 + a_kq);
        sa[1] = *(const float4*)(wb + (size_t)(m0 + a_row + 64) * S + k0 + a_kq);
        sb    = *(const float4*)(vb + (size_t)(k0 + b_k) * D + b_dq);
    };
    auto store_stage = [&](int buf) {
        *(uint4*)&As[buf][(a_row)      * PW + a_kq] = pack4(sa[0]);
        *(uint4*)&As[buf][(a_row + 64) * PW + a_kq] = pack4(sa[1]);
        uint4 p = pack4(sb);
        Bs[buf][(b_dq + 0) * PW + b_k] = p.x;
        Bs[buf][(b_dq + 1) * PW + b_k] = p.y;
        Bs[buf][(b_dq + 2) * PW + b_k] = p.z;
        Bs[buf][(b_dq + 3) * PW + b_k] = p.w;
    };
    auto compute = [&](int buf) {
        const unsigned* A = As[buf];
        const unsigned* Bb = Bs[buf];
        #pragma unroll
        for (int s = 0; s < 2; s++) {
            unsigned af[2][4];
            #pragma unroll
            for (int mi = 0; mi < 2; mi++) {
                const int m = warp_m + mi * 16;
                af[mi][0] = A[(m + g)     * PW + s * 8 + tig];
                af[mi][1] = A[(m + g + 8) * PW + s * 8 + tig];
                af[mi][2] = A[(m + g)     * PW + s * 8 + tig + 4];
                af[mi][3] = A[(m + g + 8) * PW + s * 8 + tig + 4];
            }
            #pragma unroll
            for (int nj = 0; nj < 4; nj++) {
                const int n = warp_n + nj * 8;
                unsigned b0 = Bb[(n + g) * PW + s * 8 + tig];
                unsigned b1 = Bb[(n + g) * PW + s * 8 + tig + 4];
                #pragma unroll
                for (int mi = 0; mi < 2; mi++)
                    mma_step(acc[mi][nj], af[mi], b0, b1);
            }
        }
    };

    const int T = S / BK;   // 128
    load_stage(0);
    store_stage(0);
    __syncthreads();
    for (int t = 0; t < T; t++) {
        if (t + 1 < T) load_stage((t + 1) * BK);
        compute(t & 1);
        __syncthreads();
        if (t + 1 < T) {
            store_stage((t + 1) & 1);
            __syncthreads();
        }
    }

    #pragma unroll
    for (int mi = 0; mi < 2; mi++) {
        #pragma unroll
        for (int nj = 0; nj < 4; nj++) {
            const int d  = warp_n + nj * 8 + tig * 2;
            const int s0 = m0 + warp_m + mi * 16 + g;
            const int s1 = s0 + 8;
            float2 w0 = make_float2(acc[mi][nj][0], acc[mi][nj][1]);
            float2 w1 = make_float2(acc[mi][nj][2], acc[mi][nj][3]);
            *(float2*)&g_attn[((size_t)(bb * S + s0)) * DM + h * D + d] = w0;
            *(float2*)&g_attn[((size_t)(bb * S + s1)) * DM + h * D + d] = w1;
        }
    }
}

// ---------------------------------------------------------------------------
extern "C" void kernel_launch(void* const* d_in, const int* in_sizes, int n_in,
                              void* d_out, int out_size)
{
    const float* Q  = (const float*)d_in[0];
    const float* K  = (const float*)d_in[1];
    const float* V  = (const float*)d_in[2];
    const float* Wq = (const float*)d_in[3];
    const float* bq = (const float*)d_in[4];
    const float* Wk = (const float*)d_in[5];
    const float* bk = (const float*)d_in[6];
    const float* Wv = (const float*)d_in[7];
    const float* bv = (const float*)d_in[8];
    const float* Wo = (const float*)d_in[9];
    const float* bo = (const float*)d_in[10];

    float* out     = (float*)d_out;
    float* weights = out + (size_t)B * S * DM;

    float *q_ptr, *k_ptr, *v_ptr, *attn_ptr;
    cudaGetSymbolAddress((void**)&q_ptr, g_q);
    cudaGetSymbolAddress((void**)&k_ptr, g_k);
    cudaGetSymbolAddress((void**)&v_ptr, g_v);
    cudaGetSymbolAddress((void**)&attn_ptr, g_attn);

    dim3 pgrid(DM / 128, MTOK / 128);   // (8, 32)

    proj_tc<true><<<pgrid, 256>>>(Q, Wq, bq, q_ptr);
    proj_tc<true><<<pgrid, 256>>>(K, Wk, bk, k_ptr);
    proj_tc<true><<<pgrid, 256>>>(V, Wv, bv, v_ptr);

    logits_tc<<<dim3(S / 128, S / 128, B * H), 256>>>(weights);
    softmax_kernel<<<B * H * S, 256>>>(weights);
    attnv_tc<<<dim3(S / 128, B * H), 256>>>(weights);

    proj_tc<false><<<pgrid, 256>>>(attn_ptr, Wo, bo, out);
}

// round 5
// speedup vs baseline: 2.3039x; 1.3740x over previous
#include <cuda_runtime.h>
#include <cuda_bf16.h>
#include <math.h>
#include <stdint.h>

static constexpr int B  = 2;
static constexpr int S  = 2048;
static constexpr int DM = 1024;
static constexpr int H  = 16;
static constexpr int D  = 64;
static constexpr int MTOK = B * S;     // 4096
static constexpr int NROW = B * H * S; // 65536 attention rows
static constexpr int JT   = S / 128;   // 16 j-tiles per row

// Packed scratch: one uint32 = (lo_bf16 << 16) | hi_bf16 per fp32 element.
__device__ unsigned g_Qp[MTOK * DM];
__device__ unsigned g_Kp[MTOK * DM];
__device__ unsigned g_Vp[MTOK * DM];
__device__ unsigned g_Wqp[DM * DM];
__device__ unsigned g_Wkp[DM * DM];
__device__ unsigned g_Wvp[DM * DM];
__device__ unsigned g_Wop[DM * DM];
__device__ unsigned g_q[B * H * S * D];
__device__ unsigned g_k[B * H * S * D];
__device__ unsigned g_v[B * H * S * D];
__device__ unsigned g_attnp[MTOK * DM];
__device__ float2   g_part[(size_t)NROW * JT];
__device__ float2   g_stat[NROW];

// ---------------------------------------------------------------------------
__device__ __forceinline__ unsigned pack2(float x) {
    __nv_bfloat16 h = __float2bfloat16(x);
    __nv_bfloat16 l = __float2bfloat16(x - __bfloat162float(h));
    return ((unsigned)__bfloat16_as_ushort(l) << 16) |
           (unsigned)__bfloat16_as_ushort(h);
}
__device__ __forceinline__ uint4 pack4(float4 v) {
    return make_uint4(pack2(v.x), pack2(v.y), pack2(v.z), pack2(v.w));
}

__device__ __forceinline__ void mma16(float* c, const unsigned* a,
                                      unsigned b0, unsigned b1) {
    asm volatile(
        "mma.sync.aligned.m16n8k16.row.col.f32.bf16.bf16.f32 "
        "{%0,%1,%2,%3}, {%4,%5,%6,%7}, {%8,%9}, {%0,%1,%2,%3};\n"
        : "+f"(c[0]), "+f"(c[1]), "+f"(c[2]), "+f"(c[3])
        : "r"(a[0]), "r"(a[1]), "r"(a[2]), "r"(a[3]), "r"(b0), "r"(b1));
}
__device__ __forceinline__ void mma_step(float* acc, const unsigned* af,
                                         unsigned b0, unsigned b1) {
    unsigned bhh0 = __byte_perm(b0, b0, 0x1010);
    unsigned bhh1 = __byte_perm(b1, b1, 0x1010);
    unsigned bll0 = __byte_perm(b0, b0, 0x3232);
    unsigned bll1 = __byte_perm(b1, b1, 0x3232);
    mma16(acc, af, bhh0, bhh1);
    mma16(acc, af, bll0, bll1);
}

__device__ __forceinline__ uint32_t s2u(const void* p) {
    return (uint32_t)__cvta_generic_to_shared(p);
}
__device__ __forceinline__ void cp16(uint32_t s, const void* g) {
    asm volatile("cp.async.cg.shared.global [%0], [%1], 16;\n" :: "r"(s), "l"(g));
}
#define CP_COMMIT() asm volatile("cp.async.commit_group;\n" ::: "memory")
#define CP_WAIT(n)  asm volatile("cp.async.wait_group %0;\n" :: "n"(n) : "memory")

// ---------------------------------------------------------------------------
// Pack pass: fp32 -> packed word, grid-stride over float4 chunks.
// ---------------------------------------------------------------------------
__global__ __launch_bounds__(256) void pack_kernel(
    const float4* __restrict__ src, uint4* __restrict__ dst, int n4)
{
    int i = blockIdx.x * 256 + threadIdx.x;
    if (i < n4) dst[i] = pack4(src[i]);
}

// ---------------------------------------------------------------------------
// Projection GEMM: out = X[MTOK,DM] @ W[DM,DM] + bias   (packed in, cp.async)
// 128x128 CTA, 8 warps (2x4), warp tile 64x32, 4-stage pipeline.
// ---------------------------------------------------------------------------
template <bool SPLIT>
__global__ __launch_bounds__(256, 2) void proj_tc(
    const unsigned* __restrict__ Xp, const unsigned* __restrict__ Wp,
    const float* __restrict__ bias, void* __restrict__ outv)
{
    constexpr int NS = 4, PA = 20, PB = 136;
    extern __shared__ unsigned sh[];
    unsigned* As = sh;                    // NS * 128 * PA
    unsigned* Bs = sh + NS * 128 * PA;    // NS * 16 * PB

    const int tid  = threadIdx.x;
    const int warp = tid >> 5, lane = tid & 31;
    const int g    = lane >> 2, tig = lane & 3;
    const int warp_m = (warp >> 2) * 64;
    const int warp_n = (warp & 3) * 32;
    const int m0 = blockIdx.y * 128;
    const int n0 = blockIdx.x * 128;

    float acc[4][4][4] = {};

    auto issue = [&](int t) {
        const int k0 = t * 16, buf = t & (NS - 1);
        unsigned* Ad = As + buf * 128 * PA;
        unsigned* Bd = Bs + buf * 16 * PB;
        #pragma unroll
        for (int r = 0; r < 2; r++) {
            const int c = tid + r * 256;
            const int row = c >> 2, kq = (c & 3) * 4;
            cp16(s2u(Ad + row * PA + kq), Xp + (size_t)(m0 + row) * DM + k0 + kq);
        }
        #pragma unroll
        for (int r = 0; r < 2; r++) {
            const int c = tid + r * 256;
            const int kk = c >> 5, nq = (c & 31) * 4;
            cp16(s2u(Bd + kk * PB + nq), Wp + (size_t)(k0 + kk) * DM + n0 + nq);
        }
    };
    auto compute = [&](int buf) {
        const unsigned* A  = As + buf * 128 * PA;
        const unsigned* Bb = Bs + buf * 16 * PB;
        #pragma unroll
        for (int s = 0; s < 2; s++) {
            unsigned af[4][4];
            #pragma unroll
            for (int mi = 0; mi < 4; mi++) {
                const int m = warp_m + mi * 16;
                af[mi][0] = A[(m + g)     * PA + s * 8 + tig];
                af[mi][1] = A[(m + g + 8) * PA + s * 8 + tig];
                af[mi][2] = A[(m + g)     * PA + s * 8 + tig + 4];
                af[mi][3] = A[(m + g + 8) * PA + s * 8 + tig + 4];
            }
            #pragma unroll
            for (int nj = 0; nj < 4; nj++) {
                const int n = warp_n + nj * 8;
                unsigned b0 = Bb[(s * 8 + tig)     * PB + n + g];
                unsigned b1 = Bb[(s * 8 + tig + 4) * PB + n + g];
                #pragma unroll
                for (int mi = 0; mi < 4; mi++)
                    mma_step(acc[mi][nj], af[mi], b0, b1);
            }
        }
    };

    const int T = DM / 16;   // 64
    #pragma unroll
    for (int t = 0; t < NS - 1; t++) { issue(t); CP_COMMIT(); }
    for (int t = 0; t < T; t++) {
        CP_WAIT(NS - 2);
        __syncthreads();
        if (t + NS - 1 < T) issue(t + NS - 1);
        CP_COMMIT();
        compute(t & (NS - 1));
    }

    #pragma unroll
    for (int mi = 0; mi < 4; mi++) {
        #pragma unroll
        for (int nj = 0; nj < 4; nj++) {
            const int c  = n0 + warp_n + nj * 8 + tig * 2;
            const int r0 = m0 + warp_m + mi * 16 + g;
            const int r1 = r0 + 8;
            const float bx = __ldg(&bias[c]), by = __ldg(&bias[c + 1]);
            float2 w0 = make_float2(acc[mi][nj][0] + bx, acc[mi][nj][1] + by);
            float2 w1 = make_float2(acc[mi][nj][2] + bx, acc[mi][nj][3] + by);
            if (SPLIT) {
                unsigned* out = (unsigned*)outv;
                const int h = c / D, d = c % D;
                const int b0r = r0 / S, s0r = r0 % S;
                const int b1r = r1 / S, s1r = r1 % S;
                uint2 p0 = make_uint2(pack2(w0.x), pack2(w0.y));
                uint2 p1 = make_uint2(pack2(w1.x), pack2(w1.y));
                *(uint2*)&out[(((size_t)(b0r * H + h)) * S + s0r) * D + d] = p0;
                *(uint2*)&out[(((size_t)(b1r * H + h)) * S + s1r) * D + d] = p1;
            } else {
                float* out = (float*)outv;
                *(float2*)&out[(size_t)r0 * DM + c] = w0;
                *(float2*)&out[(size_t)r1 * DM + c] = w1;
            }
        }
    }
}

// ---------------------------------------------------------------------------
// Logits + per-tile softmax partials.
// L[bh,i,j] = dot(q,k)*0.125 -> Wout; per (row, 128-col tile): (max, sumexp).
// ---------------------------------------------------------------------------
__global__ __launch_bounds__(256, 2) void logits_tc(
    float* __restrict__ Wout, float2* __restrict__ part)
{
    constexpr int PA = 68;
    extern __shared__ unsigned sh[];
    unsigned* As = sh;              // 128 * 68
    unsigned* Bs = sh + 128 * PA;   // 128 * 68
    __shared__ float2 spart[128][4];

    const int tid  = threadIdx.x;
    const int warp = tid >> 5, lane = tid & 31;
    const int g    = lane >> 2, tig = lane & 3;
    const int warp_m = (warp >> 2) * 64;
    const int warp_n = (warp & 3) * 32;
    const int wq = warp & 3;
    const int bh = blockIdx.z;
    const int i0 = blockIdx.y * 128;
    const int j0 = blockIdx.x * 128;
    const unsigned* qb = g_q + (size_t)bh * S * D;
    const unsigned* kb = g_k + (size_t)bh * S * D;

    #pragma unroll
    for (int r = 0; r < 8; r++) {
        const int c = tid + r * 256;
        const int row = c >> 4, kq = (c & 15) * 4;
        cp16(s2u(As + row * PA + kq), qb + (size_t)(i0 + row) * D + kq);
        cp16(s2u(Bs + row * PA + kq), kb + (size_t)(j0 + row) * D + kq);
    }
    CP_COMMIT();
    CP_WAIT(0);
    __syncthreads();

    float acc[4][4][4] = {};
    #pragma unroll
    for (int ks = 0; ks < 8; ks++) {
        const int kb2 = ks * 8;
        unsigned af[4][4];
        #pragma unroll
        for (int mi = 0; mi < 4; mi++) {
            const int m = warp_m + mi * 16;
            af[mi][0] = As[(m + g)     * PA + kb2 + tig];
            af[mi][1] = As[(m + g + 8) * PA + kb2 + tig];
            af[mi][2] = As[(m + g)     * PA + kb2 + tig + 4];
            af[mi][3] = As[(m + g + 8) * PA + kb2 + tig + 4];
        }
        #pragma unroll
        for (int nj = 0; nj < 4; nj++) {
            const int n = warp_n + nj * 8;
            unsigned b0 = Bs[(n + g) * PA + kb2 + tig];
            unsigned b1 = Bs[(n + g) * PA + kb2 + tig + 4];
            #pragma unroll
            for (int mi = 0; mi < 4; mi++)
                mma_step(acc[mi][nj], af[mi], b0, b1);
        }
    }

    float* outb = Wout + (size_t)bh * S * S;
    #pragma unroll
    for (int mi = 0; mi < 4; mi++) {
        #pragma unroll
        for (int nj = 0; nj < 4; nj++)
            #pragma unroll
            for (int v = 0; v < 4; v++) acc[mi][nj][v] *= 0.125f;

        // row-wise max over this warp's 32 columns
        float m0v = -1e30f, m1v = -1e30f;
        #pragma unroll
        for (int nj = 0; nj < 4; nj++) {
            m0v = fmaxf(m0v, fmaxf(acc[mi][nj][0], acc[mi][nj][1]));
            m1v = fmaxf(m1v, fmaxf(acc[mi][nj][2], acc[mi][nj][3]));
        }
        #pragma unroll
        for (int o = 1; o < 4; o <<= 1) {
            m0v = fmaxf(m0v, __shfl_xor_sync(0xffffffffu, m0v, o));
            m1v = fmaxf(m1v, __shfl_xor_sync(0xffffffffu, m1v, o));
        }
        float s0 = 0.f, s1 = 0.f;
        #pragma unroll
        for (int nj = 0; nj < 4; nj++) {
            s0 += __expf(acc[mi][nj][0] - m0v) + __expf(acc[mi][nj][1] - m0v);
            s1 += __expf(acc[mi][nj][2] - m1v) + __expf(acc[mi][nj][3] - m1v);
        }
        #pragma unroll
        for (int o = 1; o < 4; o <<= 1) {
            s0 += __shfl_xor_sync(0xffffffffu, s0, o);
            s1 += __shfl_xor_sync(0xffffffffu, s1, o);
        }
        if (tig == 0) {
            spart[warp_m + mi * 16 + g    ][wq] = make_float2(m0v, s0);
            spart[warp_m + mi * 16 + g + 8][wq] = make_float2(m1v, s1);
        }

        // store raw scaled logits
        #pragma unroll
        for (int nj = 0; nj < 4; nj++) {
            const int c  = j0 + warp_n + nj * 8 + tig * 2;
            const int r0 = i0 + warp_m + mi * 16 + g;
            *(float2*)&outb[(size_t)r0 * S + c] =
                make_float2(acc[mi][nj][0], acc[mi][nj][1]);
            *(float2*)&outb[(size_t)(r0 + 8) * S + c] =
                make_float2(acc[mi][nj][2], acc[mi][nj][3]);
        }
    }
    __syncthreads();

    if (tid < 128) {
        float2 p0 = spart[tid][0], p1 = spart[tid][1];
        float2 p2 = spart[tid][2], p3 = spart[tid][3];
        float mt = fmaxf(fmaxf(p0.x, p1.x), fmaxf(p2.x, p3.x));
        float st = p0.y * __expf(p0.x - mt) + p1.y * __expf(p1.x - mt) +
                   p2.y * __expf(p2.x - mt) + p3.y * __expf(p3.x - mt);
        part[((size_t)bh * S + i0 + tid) * JT + blockIdx.x] = make_float2(mt, st);
    }
}

// ---------------------------------------------------------------------------
// Row stats: fold 16 tile partials per row -> (max, 1/sum).
// ---------------------------------------------------------------------------
__global__ __launch_bounds__(256) void rowstat_kernel(
    const float2* __restrict__ part, float2* __restrict__ stat)
{
    const int r = blockIdx.x * 256 + threadIdx.x;
    const float2* p = part + (size_t)r * JT;
    float2 v[JT];
    float m = -1e30f;
    #pragma unroll
    for (int j = 0; j < JT; j++) { v[j] = __ldg(&p[j]); m = fmaxf(m, v[j].x); }
    float s = 0.f;
    #pragma unroll
    for (int j = 0; j < JT; j++) s += v[j].y * __expf(v[j].x - m);
    stat[r] = make_float2(m, 1.0f / s);
}

// ---------------------------------------------------------------------------
// Fused softmax-normalize + attn@V.
// Reads raw logits, computes p = exp(x-m)*inv, writes p back (final weights),
// accumulates p @ v -> packed merged attn.
// ---------------------------------------------------------------------------
__global__ __launch_bounds__(256, 2) void attnv_tc(
    float* __restrict__ Wt, const float2* __restrict__ stat)
{
    constexpr int PA = 20, PB = 72;
    __shared__ unsigned As[2][128 * PA];
    __shared__ unsigned Bs[2][16 * PB];

    const int tid  = threadIdx.x;
    const int warp = tid >> 5, lane = tid & 31;
    const int g    = lane >> 2, tig = lane & 3;
    const int warp_m = (warp >> 1) * 32;
    const int warp_n = (warp & 1) * 32;
    const int bh = blockIdx.y;
    const int m0 = blockIdx.x * 128;
    float* wb = Wt + (size_t)bh * S * S;
    const unsigned* vb = g_v + (size_t)bh * S * D;
    const int bb = bh / H, h = bh % H;

    const int a_row = tid >> 2, a_kq = (tid & 3) * 4;
    const int b_k   = tid >> 4, b_dq = (tid & 15) * 4;

    const float2 st0 = __ldg(&stat[(size_t)bh * S + m0 + a_row]);
    const float2 st1 = __ldg(&stat[(size_t)bh * S + m0 + a_row + 64]);

    float acc[2][4][4] = {};
    float4 sa[2];
    uint4  sb;

    auto load_stage = [&](int k0) {
        float* p0 = wb + (size_t)(m0 + a_row)      * S + k0 + a_kq;
        float* p1 = wb + (size_t)(m0 + a_row + 64) * S + k0 + a_kq;
        float4 x0 = *(float4*)p0;
        float4 x1 = *(float4*)p1;
        sa[0] = make_float4(__expf(x0.x - st0.x) * st0.y,
                            __expf(x0.y - st0.x) * st0.y,
                            __expf(x0.z - st0.x) * st0.y,
                            __expf(x0.w - st0.x) * st0.y);
        sa[1] = make_float4(__expf(x1.x - st1.x) * st1.y,
                            __expf(x1.y - st1.x) * st1.y,
                            __expf(x1.z - st1.x) * st1.y,
                            __expf(x1.w - st1.x) * st1.y);
        *(float4*)p0 = sa[0];   // final weights output (in place)
        *(float4*)p1 = sa[1];
        sb = *(const uint4*)(vb + (size_t)(k0 + b_k) * D + b_dq);
    };
    auto store_stage = [&](int buf) {
        *(uint4*)&As[buf][(a_row)      * PA + a_kq] = pack4(sa[0]);
        *(uint4*)&As[buf][(a_row + 64) * PA + a_kq] = pack4(sa[1]);
        *(uint4*)&Bs[buf][b_k * PB + b_dq] = sb;
    };
    auto compute = [&](int buf) {
        const unsigned* A  = As[buf];
        const unsigned* Bb = Bs[buf];
        #pragma unroll
        for (int s = 0; s < 2; s++) {
            unsigned af[2][4];
            #pragma unroll
            for (int mi = 0; mi < 2; mi++) {
                const int m = warp_m + mi * 16;
                af[mi][0] = A[(m + g)     * PA + s * 8 + tig];
                af[mi][1] = A[(m + g + 8) * PA + s * 8 + tig];
                af[mi][2] = A[(m + g)     * PA + s * 8 + tig + 4];
                af[mi][3] = A[(m + g + 8) * PA + s * 8 + tig + 4];
            }
            #pragma unroll
            for (int nj = 0; nj < 4; nj++) {
                const int n = warp_n + nj * 8;
                unsigned b0 = Bb[(s * 8 + tig)     * PB + n + g];
                unsigned b1 = Bb[(s * 8 + tig + 4) * PB + n + g];
                #pragma unroll
                for (int mi = 0; mi < 2; mi++)
                    mma_step(acc[mi][nj], af[mi], b0, b1);
            }
        }
    };

    const int T = S / 16;   // 128
    load_stage(0);
    store_stage(0);
    __syncthreads();
    for (int t = 0; t < T; t++) {
        if (t + 1 < T) load_stage((t + 1) * 16);
        compute(t & 1);
        __syncthreads();
        if (t + 1 < T) {
            store_stage((t + 1) & 1);
            __syncthreads();
        }
    }

    #pragma unroll
    for (int mi = 0; mi < 2; mi++) {
        #pragma unroll
        for (int nj = 0; nj < 4; nj++) {
            const int d  = warp_n + nj * 8 + tig * 2;
            const int s0 = m0 + warp_m + mi * 16 + g;
            const int s1 = s0 + 8;
            uint2 w0 = make_uint2(pack2(acc[mi][nj][0]), pack2(acc[mi][nj][1]));
            uint2 w1 = make_uint2(pack2(acc[mi][nj][2]), pack2(acc[mi][nj][3]));
            *(uint2*)&g_attnp[((size_t)(bb * S + s0)) * DM + h * D + d] = w0;
            *(uint2*)&g_attnp[((size_t)(bb * S + s1)) * DM + h * D + d] = w1;
        }
    }
}

// ---------------------------------------------------------------------------
extern "C" void kernel_launch(void* const* d_in, const int* in_sizes, int n_in,
                              void* d_out, int out_size)
{
    const float* Q  = (const float*)d_in[0];
    const float* K  = (const float*)d_in[1];
    const float* V  = (const float*)d_in[2];
    const float* Wq = (const float*)d_in[3];
    const float* bq = (const float*)d_in[4];
    const float* Wk = (const float*)d_in[5];
    const float* bk = (const float*)d_in[6];
    const float* Wv = (const float*)d_in[7];
    const float* bv = (const float*)d_in[8];
    const float* Wo = (const float*)d_in[9];
    const float* bo = (const float*)d_in[10];

    float* out     = (float*)d_out;
    float* weights = out + (size_t)B * S * DM;

    unsigned *Qp, *Kp, *Vp, *Wqp, *Wkp, *Wvp, *Wop, *qp, *kp, *vp, *attnp;
    float2 *part, *stat;
    cudaGetSymbolAddress((void**)&Qp, g_Qp);
    cudaGetSymbolAddress((void**)&Kp, g_Kp);
    cudaGetSymbolAddress((void**)&Vp, g_Vp);
    cudaGetSymbolAddress((void**)&Wqp, g_Wqp);
    cudaGetSymbolAddress((void**)&Wkp, g_Wkp);
    cudaGetSymbolAddress((void**)&Wvp, g_Wvp);
    cudaGetSymbolAddress((void**)&Wop, g_Wop);
    cudaGetSymbolAddress((void**)&qp, g_q);
    cudaGetSymbolAddress((void**)&kp, g_k);
    cudaGetSymbolAddress((void**)&vp, g_v);
    cudaGetSymbolAddress((void**)&attnp, g_attnp);
    cudaGetSymbolAddress((void**)&part, g_part);
    cudaGetSymbolAddress((void**)&stat, g_stat);

    const int proj_smem   = 4 * (128 * 20 + 16 * 136) * 4;   // 75776
    const int logits_smem = 2 * 128 * 68 * 4;                // 69632
    cudaFuncSetAttribute(proj_tc<true>,
        cudaFuncAttributeMaxDynamicSharedMemorySize, proj_smem);
    cudaFuncSetAttribute(proj_tc<false>,
        cudaFuncAttributeMaxDynamicSharedMemorySize, proj_smem);
    cudaFuncSetAttribute(logits_tc,
        cudaFuncAttributeMaxDynamicSharedMemorySize, logits_smem);

    // 1. pack inputs + weights
    const int nX4 = MTOK * DM / 4, nW4 = DM * DM / 4;
    pack_kernel<<<(nX4 + 255) / 256, 256>>>((const float4*)Q, (uint4*)Qp, nX4);
    pack_kernel<<<(nX4 + 255) / 256, 256>>>((const float4*)K, (uint4*)Kp, nX4);
    pack_kernel<<<(nX4 + 255) / 256, 256>>>((const float4*)V, (uint4*)Vp, nX4);
    pack_kernel<<<(nW4 + 255) / 256, 256>>>((const float4*)Wq, (uint4*)Wqp, nW4);
    pack_kernel<<<(nW4 + 255) / 256, 256>>>((const float4*)Wk, (uint4*)Wkp, nW4);
    pack_kernel<<<(nW4 + 255) / 256, 256>>>((const float4*)Wv, (uint4*)Wvp, nW4);
    pack_kernel<<<(nW4 + 255) / 256, 256>>>((const float4*)Wo, (uint4*)Wop, nW4);

    dim3 pgrid(DM / 128, MTOK / 128);   // (8, 32)

    // 2. projections (write packed head-split q/k/v)
    proj_tc<true><<<pgrid, 256, proj_smem>>>(Qp, Wqp, bq, qp);
    proj_tc<true><<<pgrid, 256, proj_smem>>>(Kp, Wkp, bk, kp);
    proj_tc<true><<<pgrid, 256, proj_smem>>>(Vp, Wvp, bv, vp);

    // 3. logits + per-tile softmax partials
    logits_tc<<<dim3(JT, S / 128, B * H), 256, logits_smem>>>(weights, part);

    // 4. row stats
    rowstat_kernel<<<NROW / 256, 256>>>(part, stat);

    // 5. fused normalize + attn@V (weights finalized in place)
    attnv_tc<<<dim3(S / 128, B * H), 256>>>(weights, stat);

    // 6. output projection
    proj_tc<false><<<pgrid, 256, proj_smem>>>(attnp, Wop, bo, out);
}

// round 6
// speedup vs baseline: 2.3139x; 1.0044x over previous
#include <cuda_runtime.h>
#include <cuda_bf16.h>
#include <math.h>
#include <stdint.h>

static constexpr int B  = 2;
static constexpr int S  = 2048;
static constexpr int DM = 1024;
static constexpr int H  = 16;
static constexpr int D  = 64;
static constexpr int MTOK = B * S;     // 4096
static constexpr int NROW = B * H * S; // 65536
static constexpr int JT   = S / 128;   // 16

// Packed scratch: uint32 = (lo_bf16 << 16) | hi_bf16 per fp32 element.
__device__ unsigned g_Qp[MTOK * DM];
__device__ unsigned g_Kp[MTOK * DM];
__device__ unsigned g_Vp[MTOK * DM];
__device__ unsigned g_Wqp[DM * DM];
__device__ unsigned g_Wkp[DM * DM];
__device__ unsigned g_Wvp[DM * DM];
__device__ unsigned g_Wop[DM * DM];
__device__ unsigned g_q[B * H * S * D];
__device__ unsigned g_k[B * H * S * D];
__device__ unsigned g_v[B * H * S * D];
__device__ unsigned g_attnp[MTOK * DM];
__device__ float2   g_part[(size_t)NROW * JT];

// ---------------------------------------------------------------------------
__device__ __forceinline__ unsigned pack2(float x) {
    __nv_bfloat16 h = __float2bfloat16(x);
    __nv_bfloat16 l = __float2bfloat16(x - __bfloat162float(h));
    return ((unsigned)__bfloat16_as_ushort(l) << 16) |
           (unsigned)__bfloat16_as_ushort(h);
}
__device__ __forceinline__ uint4 pack4(float4 v) {
    return make_uint4(pack2(v.x), pack2(v.y), pack2(v.z), pack2(v.w));
}

__device__ __forceinline__ void mma16(float* c, const unsigned* a,
                                      unsigned b0, unsigned b1) {
    asm volatile(
        "mma.sync.aligned.m16n8k16.row.col.f32.bf16.bf16.f32 "
        "{%0,%1,%2,%3}, {%4,%5,%6,%7}, {%8,%9}, {%0,%1,%2,%3};\n"
        : "+f"(c[0]), "+f"(c[1]), "+f"(c[2]), "+f"(c[3])
        : "r"(a[0]), "r"(a[1]), "r"(a[2]), "r"(a[3]), "r"(b0), "r"(b1));
}
__device__ __forceinline__ void mma_step(float* acc, const unsigned* af,
                                         unsigned b0, unsigned b1) {
    unsigned bhh0 = __byte_perm(b0, b0, 0x1010);
    unsigned bhh1 = __byte_perm(b1, b1, 0x1010);
    unsigned bll0 = __byte_perm(b0, b0, 0x3232);
    unsigned bll1 = __byte_perm(b1, b1, 0x3232);
    mma16(acc, af, bhh0, bhh1);
    mma16(acc, af, bll0, bll1);
}

__device__ __forceinline__ uint32_t s2u(const void* p) {
    return (uint32_t)__cvta_generic_to_shared(p);
}
__device__ __forceinline__ void cp16(uint32_t s, const void* g) {
    asm volatile("cp.async.cg.shared.global [%0], [%1], 16;\n" :: "r"(s), "l"(g));
}
#define CP_COMMIT() asm volatile("cp.async.commit_group;\n" ::: "memory")
#define CP_WAIT(n)  asm volatile("cp.async.wait_group %0;\n" :: "n"(n) : "memory")

__device__ __forceinline__ void ldsm_x4(unsigned* r, uint32_t addr) {
    asm volatile("ldmatrix.sync.aligned.m8n8.x4.shared.b16 {%0,%1,%2,%3}, [%4];\n"
        : "=r"(r[0]), "=r"(r[1]), "=r"(r[2]), "=r"(r[3]) : "r"(addr));
}

// A-fragment ldmatrix lane offsets for [row][k] layout (words):
//   row  += (lane&7) + ((lane>>3)&1)*8 ; col += ((lane>>4)&1)*4
// -> regs {(g,kb),(g+8,kb),(g,kb+4),(g+8,kb+4)} == scalar af[0..3].

// ---------------------------------------------------------------------------
// One fused pack pass over Q,K,V,Wq,Wk,Wv,Wo.
// ---------------------------------------------------------------------------
__global__ __launch_bounds__(256) void packall_kernel(
    const float4* __restrict__ q, const float4* __restrict__ k,
    const float4* __restrict__ v, const float4* __restrict__ wq,
    const float4* __restrict__ wk, const float4* __restrict__ wv,
    const float4* __restrict__ wo)
{
    const int i = blockIdx.x * 256 + threadIdx.x;
    const float4* src;
    uint4* dst;
    if (i < 3145728) {                       // 3 x 1048576 (inputs)
        const int seg = i >> 20, off = i & 1048575;
        src = (seg == 0 ? q : seg == 1 ? k : v) + off;
        dst = (uint4*)(seg == 0 ? g_Qp : seg == 1 ? g_Kp : g_Vp) + off;
    } else {                                 // 4 x 262144 (weights)
        const int j = i - 3145728;
        const int seg = j >> 18, off = j & 262143;
        src = (seg == 0 ? wq : seg == 1 ? wk : seg == 2 ? wv : wo) + off;
        dst = (uint4*)(seg == 0 ? g_Wqp : seg == 1 ? g_Wkp
                     : seg == 2 ? g_Wvp : g_Wop) + off;
    }
    *dst = pack4(*src);
}

// ---------------------------------------------------------------------------
// 3 projections in one launch (blockIdx.z selects Q/K/V), head-split packed out.
// 128x128 CTA, 8 warps (2x4), warp tile 64x32, 4-stage cp.async pipeline.
// ---------------------------------------------------------------------------
__global__ __launch_bounds__(256, 2) void proj3_tc(
    const unsigned* __restrict__ X0, const unsigned* __restrict__ X1,
    const unsigned* __restrict__ X2,
    const unsigned* __restrict__ W0, const unsigned* __restrict__ W1,
    const unsigned* __restrict__ W2,
    const float* __restrict__ bb0, const float* __restrict__ bb1,
    const float* __restrict__ bb2,
    unsigned* __restrict__ o0, unsigned* __restrict__ o1,
    unsigned* __restrict__ o2)
{
    constexpr int NS = 4, PA = 20, PB = 136;
    extern __shared__ unsigned sh[];
    unsigned* As = sh;
    unsigned* Bs = sh + NS * 128 * PA;
    const uint32_t As_u = s2u(As);

    const int z = blockIdx.z;
    const unsigned* Xp  = z == 0 ? X0 : z == 1 ? X1 : X2;
    const unsigned* Wp  = z == 0 ? W0 : z == 1 ? W1 : W2;
    const float* bias   = z == 0 ? bb0 : z == 1 ? bb1 : bb2;
    unsigned* out       = z == 0 ? o0 : z == 1 ? o1 : o2;

    const int tid  = threadIdx.x;
    const int warp = tid >> 5, lane = tid & 31;
    const int g    = lane >> 2, tig = lane & 3;
    const int warp_m = (warp >> 2) * 64;
    const int warp_n = (warp & 3) * 32;
    const int m0 = blockIdx.y * 128;
    const int n0 = blockIdx.x * 128;
    const int lr = (lane & 7) + ((lane >> 3) & 1) * 8;
    const int lc = ((lane >> 4) & 1) * 4;

    float acc[4][4][4] = {};

    auto issue = [&](int t) {
        const int k0 = t * 16, buf = t & (NS - 1);
        unsigned* Ad = As + buf * 128 * PA;
        unsigned* Bd = Bs + buf * 16 * PB;
        #pragma unroll
        for (int r = 0; r < 2; r++) {
            const int c = tid + r * 256;
            const int row = c >> 2, kq = (c & 3) * 4;
            cp16(s2u(Ad + row * PA + kq), Xp + (size_t)(m0 + row) * DM + k0 + kq);
        }
        #pragma unroll
        for (int r = 0; r < 2; r++) {
            const int c = tid + r * 256;
            const int kk = c >> 5, nq = (c & 31) * 4;
            cp16(s2u(Bd + kk * PB + nq), Wp + (size_t)(k0 + kk) * DM + n0 + nq);
        }
    };
    auto compute = [&](int buf) {
        const unsigned* Bb = Bs + buf * 16 * PB;
        const uint32_t Abase = As_u + (uint32_t)(buf * 128 * PA) * 4;
        #pragma unroll
        for (int s = 0; s < 2; s++) {
            unsigned af[4][4];
            #pragma unroll
            for (int mi = 0; mi < 4; mi++)
                ldsm_x4(af[mi], Abase +
                    (uint32_t)((warp_m + mi * 16 + lr) * PA + s * 8 + lc) * 4);
            #pragma unroll
            for (int nj = 0; nj < 4; nj++) {
                const int n = warp_n + nj * 8;
                unsigned b0 = Bb[(s * 8 + tig)     * PB + n + g];
                unsigned b1 = Bb[(s * 8 + tig + 4) * PB + n + g];
                #pragma unroll
                for (int mi = 0; mi < 4; mi++)
                    mma_step(acc[mi][nj], af[mi], b0, b1);
            }
        }
    };

    const int T = DM / 16;
    #pragma unroll
    for (int t = 0; t < NS - 1; t++) { issue(t); CP_COMMIT(); }
    for (int t = 0; t < T; t++) {
        CP_WAIT(NS - 2);
        __syncthreads();
        if (t + NS - 1 < T) issue(t + NS - 1);
        CP_COMMIT();
        compute(t & (NS - 1));
    }

    #pragma unroll
    for (int mi = 0; mi < 4; mi++) {
        #pragma unroll
        for (int nj = 0; nj < 4; nj++) {
            const int c  = n0 + warp_n + nj * 8 + tig * 2;
            const int r0 = m0 + warp_m + mi * 16 + g;
            const int r1 = r0 + 8;
            const float bx = __ldg(&bias[c]), by = __ldg(&bias[c + 1]);
            const int h = c / D, d = c % D;
            const int b0r = r0 / S, s0r = r0 % S;
            const int b1r = r1 / S, s1r = r1 % S;
            uint2 p0 = make_uint2(pack2(acc[mi][nj][0] + bx),
                                  pack2(acc[mi][nj][1] + by));
            uint2 p1 = make_uint2(pack2(acc[mi][nj][2] + bx),
                                  pack2(acc[mi][nj][3] + by));
            *(uint2*)&out[(((size_t)(b0r * H + h)) * S + s0r) * D + d] = p0;
            *(uint2*)&out[(((size_t)(b1r * H + h)) * S + s1r) * D + d] = p1;
        }
    }
}

// ---------------------------------------------------------------------------
// Output projection: attn_packed @ Wo + bo -> fp32 out.
// ---------------------------------------------------------------------------
__global__ __launch_bounds__(256, 2) void projO_tc(
    const unsigned* __restrict__ Xp, const unsigned* __restrict__ Wp,
    const float* __restrict__ bias, float* __restrict__ out)
{
    constexpr int NS = 4, PA = 20, PB = 136;
    extern __shared__ unsigned sh[];
    unsigned* As = sh;
    unsigned* Bs = sh + NS * 128 * PA;
    const uint32_t As_u = s2u(As);

    const int tid  = threadIdx.x;
    const int warp = tid >> 5, lane = tid & 31;
    const int g    = lane >> 2, tig = lane & 3;
    const int warp_m = (warp >> 2) * 64;
    const int warp_n = (warp & 3) * 32;
    const int m0 = blockIdx.y * 128;
    const int n0 = blockIdx.x * 128;
    const int lr = (lane & 7) + ((lane >> 3) & 1) * 8;
    const int lc = ((lane >> 4) & 1) * 4;

    float acc[4][4][4] = {};

    auto issue = [&](int t) {
        const int k0 = t * 16, buf = t & (NS - 1);
        unsigned* Ad = As + buf * 128 * PA;
        unsigned* Bd = Bs + buf * 16 * PB;
        #pragma unroll
        for (int r = 0; r < 2; r++) {
            const int c = tid + r * 256;
            const int row = c >> 2, kq = (c & 3) * 4;
            cp16(s2u(Ad + row * PA + kq), Xp + (size_t)(m0 + row) * DM + k0 + kq);
        }
        #pragma unroll
        for (int r = 0; r < 2; r++) {
            const int c = tid + r * 256;
            const int kk = c >> 5, nq = (c & 31) * 4;
            cp16(s2u(Bd + kk * PB + nq), Wp + (size_t)(k0 + kk) * DM + n0 + nq);
        }
    };
    auto compute = [&](int buf) {
        const unsigned* Bb = Bs + buf * 16 * PB;
        const uint32_t Abase = As_u + (uint32_t)(buf * 128 * PA) * 4;
        #pragma unroll
        for (int s = 0; s < 2; s++) {
            unsigned af[4][4];
            #pragma unroll
            for (int mi = 0; mi < 4; mi++)
                ldsm_x4(af[mi], Abase +
                    (uint32_t)((warp_m + mi * 16 + lr) * PA + s * 8 + lc) * 4);
            #pragma unroll
            for (int nj = 0; nj < 4; nj++) {
                const int n = warp_n + nj * 8;
                unsigned b0 = Bb[(s * 8 + tig)     * PB + n + g];
                unsigned b1 = Bb[(s * 8 + tig + 4) * PB + n + g];
                #pragma unroll
                for (int mi = 0; mi < 4; mi++)
                    mma_step(acc[mi][nj], af[mi], b0, b1);
            }
        }
    };

    const int T = DM / 16;
    #pragma unroll
    for (int t = 0; t < NS - 1; t++) { issue(t); CP_COMMIT(); }
    for (int t = 0; t < T; t++) {
        CP_WAIT(NS - 2);
        __syncthreads();
        if (t + NS - 1 < T) issue(t + NS - 1);
        CP_COMMIT();
        compute(t & (NS - 1));
    }

    #pragma unroll
    for (int mi = 0; mi < 4; mi++) {
        #pragma unroll
        for (int nj = 0; nj < 4; nj++) {
            const int c  = n0 + warp_n + nj * 8 + tig * 2;
            const int r0 = m0 + warp_m + mi * 16 + g;
            const int r1 = r0 + 8;
            const float bx = __ldg(&bias[c]), by = __ldg(&bias[c + 1]);
            *(float2*)&out[(size_t)r0 * DM + c] =
                make_float2(acc[mi][nj][0] + bx, acc[mi][nj][1] + by);
            *(float2*)&out[(size_t)r1 * DM + c] =
                make_float2(acc[mi][nj][2] + bx, acc[mi][nj][3] + by);
        }
    }
}

// ---------------------------------------------------------------------------
// Logits + per-tile softmax partials (ldmatrix both operands).
// ---------------------------------------------------------------------------
__global__ __launch_bounds__(256, 2) void logits_tc(
    float* __restrict__ Wout, float2* __restrict__ part)
{
    constexpr int PA = 68;
    extern __shared__ unsigned sh[];
    unsigned* As = sh;
    unsigned* Bs = sh + 128 * PA;
    __shared__ float2 spart[128][4];
    const uint32_t As_u = s2u(As), Bs_u = s2u(Bs);

    const int tid  = threadIdx.x;
    const int warp = tid >> 5, lane = tid & 31;
    const int g    = lane >> 2, tig = lane & 3;
    const int warp_m = (warp >> 2) * 64;
    const int warp_n = (warp & 3) * 32;
    const int wq = warp & 3;
    const int bh = blockIdx.z;
    const int i0 = blockIdx.y * 128;
    const int j0 = blockIdx.x * 128;
    const unsigned* qb = g_q + (size_t)bh * S * D;
    const unsigned* kb = g_k + (size_t)bh * S * D;

    // A-fragment lane offsets
    const int lr = (lane & 7) + ((lane >> 3) & 1) * 8;
    const int lc = ((lane >> 4) & 1) * 4;
    // B x4 lane offsets (pair of nj per load)
    const int br = (lane & 7) + ((lane >> 4) & 1) * 8;
    const int bc = ((lane >> 3) & 1) * 4;

    #pragma unroll
    for (int r = 0; r < 8; r++) {
        const int c = tid + r * 256;
        const int row = c >> 4, kq = (c & 15) * 4;
        cp16(s2u(As + row * PA + kq), qb + (size_t)(i0 + row) * D + kq);
        cp16(s2u(Bs + row * PA + kq), kb + (size_t)(j0 + row) * D + kq);
    }
    CP_COMMIT();
    CP_WAIT(0);
    __syncthreads();

    float acc[4][4][4] = {};
    #pragma unroll
    for (int ks = 0; ks < 8; ks++) {
        const int kb2 = ks * 8;
        unsigned af[4][4];
        #pragma unroll
        for (int mi = 0; mi < 4; mi++)
            ldsm_x4(af[mi], As_u +
                (uint32_t)((warp_m + mi * 16 + lr) * PA + kb2 + lc) * 4);
        #pragma unroll
        for (int njp = 0; njp < 2; njp++) {
            unsigned bf[4];
            ldsm_x4(bf, Bs_u +
                (uint32_t)((warp_n + njp * 16 + br) * PA + kb2 + bc) * 4);
            #pragma unroll
            for (int mi = 0; mi < 4; mi++) {
                mma_step(acc[mi][njp * 2],     af[mi], bf[0], bf[1]);
                mma_step(acc[mi][njp * 2 + 1], af[mi], bf[2], bf[3]);
            }
        }
    }

    float* outb = Wout + (size_t)bh * S * S;
    #pragma unroll
    for (int mi = 0; mi < 4; mi++) {
        #pragma unroll
        for (int nj = 0; nj < 4; nj++)
            #pragma unroll
            for (int v = 0; v < 4; v++) acc[mi][nj][v] *= 0.125f;

        float m0v = -1e30f, m1v = -1e30f;
        #pragma unroll
        for (int nj = 0; nj < 4; nj++) {
            m0v = fmaxf(m0v, fmaxf(acc[mi][nj][0], acc[mi][nj][1]));
            m1v = fmaxf(m1v, fmaxf(acc[mi][nj][2], acc[mi][nj][3]));
        }
        #pragma unroll
        for (int o = 1; o < 4; o <<= 1) {
            m0v = fmaxf(m0v, __shfl_xor_sync(0xffffffffu, m0v, o));
            m1v = fmaxf(m1v, __shfl_xor_sync(0xffffffffu, m1v, o));
        }
        float s0 = 0.f, s1 = 0.f;
        #pragma unroll
        for (int nj = 0; nj < 4; nj++) {
            s0 += __expf(acc[mi][nj][0] - m0v) + __expf(acc[mi][nj][1] - m0v);
            s1 += __expf(acc[mi][nj][2] - m1v) + __expf(acc[mi][nj][3] - m1v);
        }
        #pragma unroll
        for (int o = 1; o < 4; o <<= 1) {
            s0 += __shfl_xor_sync(0xffffffffu, s0, o);
            s1 += __shfl_xor_sync(0xffffffffu, s1, o);
        }
        if (tig == 0) {
            spart[warp_m + mi * 16 + g    ][wq] = make_float2(m0v, s0);
            spart[warp_m + mi * 16 + g + 8][wq] = make_float2(m1v, s1);
        }

        #pragma unroll
        for (int nj = 0; nj < 4; nj++) {
            const int c  = j0 + warp_n + nj * 8 + tig * 2;
            const int r0 = i0 + warp_m + mi * 16 + g;
            __stcs((float2*)&outb[(size_t)r0 * S + c],
                   make_float2(acc[mi][nj][0], acc[mi][nj][1]));
            __stcs((float2*)&outb[(size_t)(r0 + 8) * S + c],
                   make_float2(acc[mi][nj][2], acc[mi][nj][3]));
        }
    }
    __syncthreads();

    if (tid < 128) {
        float2 p0 = spart[tid][0], p1 = spart[tid][1];
        float2 p2 = spart[tid][2], p3 = spart[tid][3];
        float mt = fmaxf(fmaxf(p0.x, p1.x), fmaxf(p2.x, p3.x));
        float st = p0.y * __expf(p0.x - mt) + p1.y * __expf(p1.x - mt) +
                   p2.y * __expf(p2.x - mt) + p3.y * __expf(p3.x - mt);
        part[((size_t)bh * S + i0 + tid) * JT + blockIdx.x] = make_float2(mt, st);
    }
}

// ---------------------------------------------------------------------------
// Fused rowstats + softmax-normalize + attn@V. Single sync per iteration.
// ---------------------------------------------------------------------------
__global__ __launch_bounds__(256, 2) void attnv_tc(
    float* __restrict__ Wt, const float2* __restrict__ part)
{
    constexpr int PA = 20, PB = 72;
    __shared__ unsigned As[2][128 * PA];
    __shared__ unsigned Bs[2][16 * PB];
    __shared__ float2 sstat[128];
    const uint32_t As_u = s2u(As);

    const int tid  = threadIdx.x;
    const int warp = tid >> 5, lane = tid & 31;
    const int g    = lane >> 2, tig = lane & 3;
    const int warp_m = (warp >> 1) * 32;
    const int warp_n = (warp & 1) * 32;
    const int bh = blockIdx.y;
    const int m0 = blockIdx.x * 128;
    float* wb = Wt + (size_t)bh * S * S;
    const unsigned* vb = g_v + (size_t)bh * S * D;
    const int bb = bh / H, h = bh % H;
    const int lr = (lane & 7) + ((lane >> 3) & 1) * 8;
    const int lc = ((lane >> 4) & 1) * 4;

    // Fold this CTA's 128 rows of softmax partials -> (max, 1/sum).
    if (tid < 128) {
        const float2* pp = part + ((size_t)bh * S + m0 + tid) * JT;
        float2 vv[JT];
        float mv = -1e30f;
        #pragma unroll
        for (int j = 0; j < JT; j++) { vv[j] = __ldg(&pp[j]); mv = fmaxf(mv, vv[j].x); }
        float sv = 0.f;
        #pragma unroll
        for (int j = 0; j < JT; j++) sv += vv[j].y * __expf(vv[j].x - mv);
        sstat[tid] = make_float2(mv, 1.0f / sv);
    }
    __syncthreads();

    const int a_row = tid >> 2, a_kq = (tid & 3) * 4;
    const int b_k   = tid >> 4, b_dq = (tid & 15) * 4;
    const float2 st0 = sstat[a_row];
    const float2 st1 = sstat[a_row + 64];

    float acc[2][4][4] = {};
    float4 sa[2];
    uint4  sb;

    auto load_stage = [&](int k0) {
        float* p0 = wb + (size_t)(m0 + a_row)      * S + k0 + a_kq;
        float* p1 = wb + (size_t)(m0 + a_row + 64) * S + k0 + a_kq;
        float4 x0 = __ldcs((const float4*)p0);
        float4 x1 = __ldcs((const float4*)p1);
        sa[0] = make_float4(__expf(x0.x - st0.x) * st0.y,
                            __expf(x0.y - st0.x) * st0.y,
                            __expf(x0.z - st0.x) * st0.y,
                            __expf(x0.w - st0.x) * st0.y);
        sa[1] = make_float4(__expf(x1.x - st1.x) * st1.y,
                            __expf(x1.y - st1.x) * st1.y,
                            __expf(x1.z - st1.x) * st1.y,
                            __expf(x1.w - st1.x) * st1.y);
        __stcs((float4*)p0, sa[0]);   // final weights (in place)
        __stcs((float4*)p1, sa[1]);
        sb = *(const uint4*)(vb + (size_t)(k0 + b_k) * D + b_dq);
    };
    auto store_stage = [&](int buf) {
        *(uint4*)&As[buf][(a_row)      * PA + a_kq] = pack4(sa[0]);
        *(uint4*)&As[buf][(a_row + 64) * PA + a_kq] = pack4(sa[1]);
        *(uint4*)&Bs[buf][b_k * PB + b_dq] = sb;
    };
    auto compute = [&](int buf) {
        const unsigned* Bb = Bs[buf];
        const uint32_t Abase = As_u + (uint32_t)(buf * 128 * PA) * 4;
        #pragma unroll
        for (int s = 0; s < 2; s++) {
            unsigned af[2][4];
            #pragma unroll
            for (int mi = 0; mi < 2; mi++)
                ldsm_x4(af[mi], Abase +
                    (uint32_t)((warp_m + mi * 16 + lr) * PA + s * 8 + lc) * 4);
            #pragma unroll
            for (int nj = 0; nj < 4; nj++) {
                const int n = warp_n + nj * 8;
                unsigned b0 = Bb[(s * 8 + tig)     * PB + n + g];
                unsigned b1 = Bb[(s * 8 + tig + 4) * PB + n + g];
                #pragma unroll
                for (int mi = 0; mi < 2; mi++)
                    mma_step(acc[mi][nj], af[mi], b0, b1);
            }
        }
    };

    const int T = S / 16;   // 128
    load_stage(0);
    store_stage(0);
    __syncthreads();
    for (int t = 0; t < T; t++) {
        if (t + 1 < T) load_stage((t + 1) * 16);
        compute(t & 1);
        if (t + 1 < T) {
            store_stage((t + 1) & 1);
            __syncthreads();
        }
    }

    #pragma unroll
    for (int mi = 0; mi < 2; mi++) {
        #pragma unroll
        for (int nj = 0; nj < 4; nj++) {
            const int d  = warp_n + nj * 8 + tig * 2;
            const int s0 = m0 + warp_m + mi * 16 + g;
            const int s1 = s0 + 8;
            uint2 w0 = make_uint2(pack2(acc[mi][nj][0]), pack2(acc[mi][nj][1]));
            uint2 w1 = make_uint2(pack2(acc[mi][nj][2]), pack2(acc[mi][nj][3]));
            *(uint2*)&g_attnp[((size_t)(bb * S + s0)) * DM + h * D + d] = w0;
            *(uint2*)&g_attnp[((size_t)(bb * S + s1)) * DM + h * D + d] = w1;
        }
    }
}

// ---------------------------------------------------------------------------
extern "C" void kernel_launch(void* const* d_in, const int* in_sizes, int n_in,
                              void* d_out, int out_size)
{
    const float* Q  = (const float*)d_in[0];
    const float* K  = (const float*)d_in[1];
    const float* V  = (const float*)d_in[2];
    const float* Wq = (const float*)d_in[3];
    const float* bq = (const float*)d_in[4];
    const float* Wk = (const float*)d_in[5];
    const float* bk = (const float*)d_in[6];
    const float* Wv = (const float*)d_in[7];
    const float* bv = (const float*)d_in[8];
    const float* Wo = (const float*)d_in[9];
    const float* bo = (const float*)d_in[10];

    float* out     = (float*)d_out;
    float* weights = out + (size_t)B * S * DM;

    unsigned *Qp, *Kp, *Vp, *Wqp, *Wkp, *Wvp, *Wop, *qp, *kp, *vp, *attnp;
    float2 *part;
    cudaGetSymbolAddress((void**)&Qp, g_Qp);
    cudaGetSymbolAddress((void**)&Kp, g_Kp);
    cudaGetSymbolAddress((void**)&Vp, g_Vp);
    cudaGetSymbolAddress((void**)&Wqp, g_Wqp);
    cudaGetSymbolAddress((void**)&Wkp, g_Wkp);
    cudaGetSymbolAddress((void**)&Wvp, g_Wvp);
    cudaGetSymbolAddress((void**)&Wop, g_Wop);
    cudaGetSymbolAddress((void**)&qp, g_q);
    cudaGetSymbolAddress((void**)&kp, g_k);
    cudaGetSymbolAddress((void**)&vp, g_v);
    cudaGetSymbolAddress((void**)&attnp, g_attnp);
    cudaGetSymbolAddress((void**)&part, g_part);

    const int proj_smem   = 4 * (128 * 20 + 16 * 136) * 4;   // 75776
    const int logits_smem = 2 * 128 * 68 * 4;                // 69632
    cudaFuncSetAttribute(proj3_tc,
        cudaFuncAttributeMaxDynamicSharedMemorySize, proj_smem);
    cudaFuncSetAttribute(projO_tc,
        cudaFuncAttributeMaxDynamicSharedMemorySize, proj_smem);
    cudaFuncSetAttribute(logits_tc,
        cudaFuncAttributeMaxDynamicSharedMemorySize, logits_smem);

    // 1. one fused pack pass
    packall_kernel<<<16384, 256>>>((const float4*)Q, (const float4*)K,
                                   (const float4*)V, (const float4*)Wq,
                                   (const float4*)Wk, (const float4*)Wv,
                                   (const float4*)Wo);

    // 2. all three projections in one launch
    proj3_tc<<<dim3(DM / 128, MTOK / 128, 3), 256, proj_smem>>>(
        Qp, Kp, Vp, Wqp, Wkp, Wvp, bq, bk, bv, qp, kp, vp);

    // 3. logits + partials
    logits_tc<<<dim3(JT, S / 128, B * H), 256, logits_smem>>>(weights, part);

    // 4. fused rowstats + normalize + attn@V
    attnv_tc<<<dim3(S / 128, B * H), 256>>>(weights, part);

    // 5. output projection
    projO_tc<<<dim3(DM / 128, MTOK / 128), 256, proj_smem>>>(attnp, Wop, bo, out);
}